// round 8
// baseline (speedup 1.0000x reference)
#include <cuda_runtime.h>
#include <cuda_fp16.h>
#include <cstdint>
#include <math.h>

#define BATCH   16384
#define TSTEPS  28
#define FEAT    28
#define HID     128
#define G3      384
#define NCLS    10

#define TILE_B  32
#define NTH     256
#define NKT     10          // K chunks of 16: kt 0..7 = h (k=j), kt 8,9 = x
#define NBLK    (BATCH / TILE_B)
#define NBFR    (8 * NKT * 4 * 2 * 32)

// B operand, fragment-linear, split hi/lo arrays:
// index [w(8)][kt(10)][g(4)][nt(2)][lane(32)] : uint2 {b0, b1}
__device__ __align__(16) uint2 gB_hi[NBFR];
__device__ __align__(16) uint2 gB_lo[NBFR];

__device__ __forceinline__ uint32_t pack_h2(float a, float b) {
    __half2 p = __floats2half2_rn(a, b);
    return *reinterpret_cast<uint32_t*>(&p);
}
__device__ __forceinline__ float2 unpack_h2(uint32_t u) {
    __half2 p = *reinterpret_cast<__half2*>(&u);
    return __half22float2(p);
}

__device__ __forceinline__ void mma16816(float* c, const uint4& a,
                                         uint32_t b0, uint32_t b1) {
    asm volatile(
        "mma.sync.aligned.m16n8k16.row.col.f32.f16.f16.f32 "
        "{%0,%1,%2,%3}, {%4,%5,%6,%7}, {%8,%9}, {%0,%1,%2,%3};"
        : "+f"(c[0]), "+f"(c[1]), "+f"(c[2]), "+f"(c[3])
        : "r"(a.x), "r"(a.y), "r"(a.z), "r"(a.w), "r"(b0), "r"(b1));
}

__device__ __forceinline__ float sig_(float v) { return 1.0f / (1.0f + __expf(-v)); }
__device__ __forceinline__ float tanh_(float v) {
    float t = __expf(-2.0f * fabsf(v));
    float r = (1.0f - t) / (1.0f + t);
    return v < 0.0f ? -r : r;
}

// ---------------------------------------------------------------------------
// Prep: weights -> fragment-linear fp16 hi/lo (separate arrays).
// g: 0=z(col j), 1=r(col 128+j), 2=rh(col 256+j, R rows), 3=xh(col 256+j, W rows)
// ---------------------------------------------------------------------------
__global__ void prep_B(const float* __restrict__ Rk, const float* __restrict__ Wk) {
    int idx = blockIdx.x * blockDim.x + threadIdx.x;
    if (idx >= NBFR) return;
    int lane = idx & 31;
    int nt   = (idx >> 5) & 1;
    int g    = (idx >> 6) & 3;
    int kt   = (idx >> 8) % NKT;
    int w    = (idx >> 8) / NKT;
    int gid  = lane >> 2, tg = lane & 3;

    int jloc = 16 * w + 8 * nt + gid;
    int wcol = (g == 0) ? jloc : (g == 1 ? 128 + jloc : 256 + jloc);
    int k0   = kt * 16 + tg * 2;

    float v[4];
#pragma unroll
    for (int i = 0; i < 4; i++) {
        int k = k0 + (i >> 1) * 8 + (i & 1);
        float val = 0.0f;
        if (k < HID) { if (g != 3) val = Rk[k * G3 + wcol]; }
        else { int f = k - HID; if (f < FEAT && g != 2) val = Wk[f * G3 + wcol]; }
        v[i] = val;
    }
    __half h[4], l[4];
#pragma unroll
    for (int i = 0; i < 4; i++) {
        h[i] = __float2half_rn(v[i]);
        l[i] = __float2half_rn(v[i] - __half2float(h[i]));
    }
    uint2 fh, fl;
    fh.x = (uint32_t)(*(unsigned short*)&h[0]) | ((uint32_t)(*(unsigned short*)&h[1]) << 16);
    fh.y = (uint32_t)(*(unsigned short*)&h[2]) | ((uint32_t)(*(unsigned short*)&h[3]) << 16);
    fl.x = (uint32_t)(*(unsigned short*)&l[0]) | ((uint32_t)(*(unsigned short*)&l[1]) << 16);
    fl.y = (uint32_t)(*(unsigned short*)&l[2]) | ((uint32_t)(*(unsigned short*)&l[3]) << 16);
    gB_hi[idx] = fh;
    gB_lo[idx] = fl;
}

// ---------------------------------------------------------------------------
// Main fused GRU: persistent per-block scan, HMMA core.
// Round 8: pass-major MMA issue order -> accumulator reuse distance 12.
// ---------------------------------------------------------------------------
__global__ void __launch_bounds__(NTH, 2)
gru_hmma_kernel(const float* __restrict__ x,
                const float* __restrict__ bias,
                const float* __restrict__ dw,
                const float* __restrict__ db,
                float* __restrict__ out)
{
    __shared__ uint4 Ah[2][NKT][2][32];
    __shared__ float hs[TILE_B][HID + 1];

    const int tid  = threadIdx.x;
    const int wid  = tid >> 5;
    const int lane = tid & 31;
    const int gid  = lane >> 2;
    const int tg   = lane & 3;
    const int b0   = blockIdx.x * TILE_B;
    const float* xg = x + (size_t)b0 * (TSTEPS * FEAT);

    for (int i = tid; i < 2 * NKT * 2 * 32; i += NTH)
        ((uint4*)Ah)[i] = make_uint4(0, 0, 0, 0);

    // bias -> accumulator-init registers: bp[u][e], u = g*2+nt
    float bp[8][2];
#pragma unroll
    for (int g = 0; g < 4; g++)
#pragma unroll
        for (int nt = 0; nt < 2; nt++) {
            int jl = 16 * wid + 8 * nt + 2 * tg;
#pragma unroll
            for (int e = 0; e < 2; e++) {
                int j = jl + e;
                float v;
                if      (g == 0) v = bias[j]       + bias[G3 + j];
                else if (g == 1) v = bias[128 + j] + bias[G3 + 128 + j];
                else if (g == 2) v = bias[G3 + 256 + j];
                else             v = bias[256 + j];
                bp[g * 2 + nt][e] = v;
            }
        }
    __syncthreads();

    auto stage_x = [&](int t) {
#pragma unroll
        for (int i = 0; i < 2; i++) {
            int s   = tid * 2 + i;
            int r   = s & 3;
            int ln  = (s >> 2) & 31;
            int mt  = (s >> 7) & 1;
            int kt8 = s >> 8;
            int gd = ln >> 2, tgg = ln & 3;
            int row = mt * 16 + gd + 8 * (r & 1);
            int kl  = kt8 * 16 + tgg * 2 + 8 * (r >> 1);
            float v0 = 0.0f, v1 = 0.0f;
            if (kl < FEAT) {
                const float* p = xg + (size_t)row * (TSTEPS * FEAT) + t * FEAT + kl;
                v0 = p[0];
                if (kl + 1 < FEAT) v1 = p[1];
            }
            __half h0 = __float2half_rn(v0), h1 = __float2half_rn(v1);
            float l0 = v0 - __half2float(h0), l1 = v1 - __half2float(h1);
            ((uint32_t*)&Ah[0][8 + kt8][mt][ln])[r] =
                (uint32_t)(*(unsigned short*)&h0) | ((uint32_t)(*(unsigned short*)&h1) << 16);
            ((uint32_t*)&Ah[1][8 + kt8][mt][ln])[r] = pack_h2(l0, l1);
        }
    };
    stage_x(0);
    __syncthreads();

    float acc[2][8][4];

    for (int t = 0; t < TSTEPS; t++) {
#pragma unroll
        for (int mt = 0; mt < 2; mt++)
#pragma unroll
            for (int u = 0; u < 8; u++) {
                acc[mt][u][0] = bp[u][0]; acc[mt][u][1] = bp[u][1];
                acc[mt][u][2] = bp[u][0]; acc[mt][u][3] = bp[u][1];
            }

        // ---- HMMA mainloop: pass-major issue order ----
#pragma unroll
        for (int kt = 0; kt < NKT; kt++) {
            const uint4 Ah0 = Ah[0][kt][0][lane];
            const uint4 Ah1 = Ah[0][kt][1][lane];
            const uint4 Al0 = Ah[1][kt][0][lane];
            const uint4 Al1 = Ah[1][kt][1][lane];
            // active gate groups: kt<8 -> {z, r, rh}; kt>=8 -> {z, r, xh}
            const int g2 = (kt < 8) ? 2 : 3;
            const int gs[3] = {0, 1, g2};

            // load all B frags for this kt (6 hi + 6 lo uint2)
            uint2 Bh[3][2], Bl[3][2];
#pragma unroll
            for (int gi = 0; gi < 3; gi++) {
                const int base = (((wid * NKT + kt) * 4 + gs[gi]) * 2) * 32 + lane;
                Bh[gi][0] = __ldg(&gB_hi[base]);
                Bh[gi][1] = __ldg(&gB_hi[base + 32]);
                Bl[gi][0] = __ldcg(&gB_lo[base]);
                Bl[gi][1] = __ldcg(&gB_lo[base + 32]);
            }

            // pass 1: Ahi * Bhi  (12 independent accumulators)
#pragma unroll
            for (int gi = 0; gi < 3; gi++)
#pragma unroll
                for (int nt = 0; nt < 2; nt++) {
                    const int u = gs[gi] * 2 + nt;
                    mma16816(acc[0][u], Ah0, Bh[gi][nt].x, Bh[gi][nt].y);
                    mma16816(acc[1][u], Ah1, Bh[gi][nt].x, Bh[gi][nt].y);
                }
            // pass 2: Alo * Bhi
#pragma unroll
            for (int gi = 0; gi < 3; gi++)
#pragma unroll
                for (int nt = 0; nt < 2; nt++) {
                    const int u = gs[gi] * 2 + nt;
                    mma16816(acc[0][u], Al0, Bh[gi][nt].x, Bh[gi][nt].y);
                    mma16816(acc[1][u], Al1, Bh[gi][nt].x, Bh[gi][nt].y);
                }
            // pass 3: Ahi * Blo
#pragma unroll
            for (int gi = 0; gi < 3; gi++)
#pragma unroll
                for (int nt = 0; nt < 2; nt++) {
                    const int u = gs[gi] * 2 + nt;
                    mma16816(acc[0][u], Ah0, Bl[gi][nt].x, Bl[gi][nt].y);
                    mma16816(acc[1][u], Ah1, Bl[gi][nt].x, Bl[gi][nt].y);
                }
        }
        __syncthreads();   // all warps done reading A frags

        // ---- epilogue: gates in-register; commit new h frags (kt = wid) ----
#pragma unroll
        for (int mt = 0; mt < 2; mt++) {
            uint4 Hh = Ah[0][wid][mt][lane];
            uint4 Hl = Ah[1][wid][mt][lane];
            const uint32_t hh_[4] = {Hh.x, Hh.y, Hh.z, Hh.w};
            const uint32_t hl_[4] = {Hl.x, Hl.y, Hl.z, Hl.w};
            uint32_t nh[4], nl[4];
#pragma unroll
            for (int r = 0; r < 4; r++) {
                const int nt = r >> 1;
                const int ci = (r & 1) * 2;
                float2 oh = unpack_h2(hh_[r]);
                float2 ol = unpack_h2(hl_[r]);
                float hold[2] = {oh.x + ol.x, oh.y + ol.y};
                float hnew[2];
#pragma unroll
                for (int e = 0; e < 2; e++) {
                    float z  = sig_(acc[mt][0 + nt][ci + e]);
                    float rr = sig_(acc[mt][2 + nt][ci + e]);
                    float hc = tanh_(acc[mt][6 + nt][ci + e] + rr * acc[mt][4 + nt][ci + e]);
                    hnew[e] = z * hold[e] + (1.0f - z) * hc;
                    if (t == TSTEPS - 1) {
                        int row = mt * 16 + gid + 8 * (r & 1);
                        int j   = 16 * wid + 8 * nt + 2 * tg + e;
                        hs[row][j] = hnew[e];
                    }
                }
                __half p0 = __float2half_rn(hnew[0]), p1 = __float2half_rn(hnew[1]);
                float r0 = hnew[0] - __half2float(p0), r1 = hnew[1] - __half2float(p1);
                nh[r] = (uint32_t)(*(unsigned short*)&p0) |
                        ((uint32_t)(*(unsigned short*)&p1) << 16);
                nl[r] = pack_h2(r0, r1);
            }
            Ah[0][wid][mt][lane] = make_uint4(nh[0], nh[1], nh[2], nh[3]);
            Ah[1][wid][mt][lane] = make_uint4(nl[0], nl[1], nl[2], nl[3]);
        }

        if (t < TSTEPS - 1) stage_x(t + 1);
        __syncthreads();   // new A frags visible to all warps
    }

    // ---- dense + softmax ----
    if (tid < TILE_B) {
        const int row = tid;
        float lg[NCLS];
#pragma unroll
        for (int c = 0; c < NCLS; c++) lg[c] = db[c];
        for (int j = 0; j < HID; j++) {
            float hv = hs[row][j];
#pragma unroll
            for (int c = 0; c < NCLS; c++) lg[c] = fmaf(hv, dw[j * NCLS + c], lg[c]);
        }
        float m = lg[0];
#pragma unroll
        for (int c = 1; c < NCLS; c++) m = fmaxf(m, lg[c]);
        float s = 0.0f;
#pragma unroll
        for (int c = 0; c < NCLS; c++) { lg[c] = expf(lg[c] - m); s += lg[c]; }
        float inv = 1.0f / s;
#pragma unroll
        for (int c = 0; c < NCLS; c++)
            out[(size_t)(b0 + row) * NCLS + c] = lg[c] * inv;
    }
}

extern "C" void kernel_launch(void* const* d_in, const int* in_sizes, int n_in,
                              void* d_out, int out_size) {
    const float* x    = (const float*)d_in[0];
    const float* Wk   = (const float*)d_in[1];
    const float* Rk   = (const float*)d_in[2];
    const float* bias = (const float*)d_in[3];
    const float* dw   = (const float*)d_in[4];
    const float* db   = (const float*)d_in[5];
    float* out = (float*)d_out;

    prep_B<<<(NBFR + 255) / 256, 256>>>(Rk, Wk);
    gru_hmma_kernel<<<NBLK, NTH>>>(x, bias, dw, db, out);
}

// round 9
// speedup vs baseline: 1.2827x; 1.2827x over previous
#include <cuda_runtime.h>
#include <cuda_fp16.h>
#include <cstdint>
#include <math.h>

#define BATCH   16384
#define TSTEPS  28
#define FEAT    28
#define HID     128
#define G3      384
#define NCLS    10

#define TILE_B  32
#define NTH     256
#define NKT     10          // K chunks of 16: kt 0..7 = h (k=j), kt 8,9 = x
#define NBLK    (BATCH / TILE_B)
#define NBFR    (8 * NKT * 4 * 2 * 32)

// B operand (hi only), fragment-linear:
// index [w(8)][kt(10)][g(4)][nt(2)][lane(32)] : uint2 {b0, b1}
__device__ __align__(16) uint2 gB_hi[NBFR];

__device__ __forceinline__ uint32_t pack_h2(float a, float b) {
    __half2 p = __floats2half2_rn(a, b);
    return *reinterpret_cast<uint32_t*>(&p);
}
__device__ __forceinline__ float2 unpack_h2(uint32_t u) {
    __half2 p = *reinterpret_cast<__half2*>(&u);
    return __half22float2(p);
}

__device__ __forceinline__ void mma16816(float* c, const uint4& a,
                                         uint32_t b0, uint32_t b1) {
    asm volatile(
        "mma.sync.aligned.m16n8k16.row.col.f32.f16.f16.f32 "
        "{%0,%1,%2,%3}, {%4,%5,%6,%7}, {%8,%9}, {%0,%1,%2,%3};"
        : "+f"(c[0]), "+f"(c[1]), "+f"(c[2]), "+f"(c[3])
        : "r"(a.x), "r"(a.y), "r"(a.z), "r"(a.w), "r"(b0), "r"(b1));
}

__device__ __forceinline__ float sig_(float v) { return 1.0f / (1.0f + __expf(-v)); }
__device__ __forceinline__ float tanh_(float v) {
    float t = __expf(-2.0f * fabsf(v));
    float r = (1.0f - t) / (1.0f + t);
    return v < 0.0f ? -r : r;
}

// ---------------------------------------------------------------------------
// Prep: weights -> fragment-linear fp16 (round-to-nearest).
// g: 0=z(col j), 1=r(col 128+j), 2=rh(col 256+j, R rows), 3=xh(col 256+j, W rows)
// ---------------------------------------------------------------------------
__global__ void prep_B(const float* __restrict__ Rk, const float* __restrict__ Wk) {
    int idx = blockIdx.x * blockDim.x + threadIdx.x;
    if (idx >= NBFR) return;
    int lane = idx & 31;
    int nt   = (idx >> 5) & 1;
    int g    = (idx >> 6) & 3;
    int kt   = (idx >> 8) % NKT;
    int w    = (idx >> 8) / NKT;
    int gid  = lane >> 2, tg = lane & 3;

    int jloc = 16 * w + 8 * nt + gid;
    int wcol = (g == 0) ? jloc : (g == 1 ? 128 + jloc : 256 + jloc);
    int k0   = kt * 16 + tg * 2;

    float v[4];
#pragma unroll
    for (int i = 0; i < 4; i++) {
        int k = k0 + (i >> 1) * 8 + (i & 1);
        float val = 0.0f;
        if (k < HID) { if (g != 3) val = Rk[k * G3 + wcol]; }
        else { int f = k - HID; if (f < FEAT && g != 2) val = Wk[f * G3 + wcol]; }
        v[i] = val;
    }
    __half h[4];
#pragma unroll
    for (int i = 0; i < 4; i++) h[i] = __float2half_rn(v[i]);
    uint2 fh;
    fh.x = (uint32_t)(*(unsigned short*)&h[0]) | ((uint32_t)(*(unsigned short*)&h[1]) << 16);
    fh.y = (uint32_t)(*(unsigned short*)&h[2]) | ((uint32_t)(*(unsigned short*)&h[3]) << 16);
    gB_hi[idx] = fh;
}

// ---------------------------------------------------------------------------
// Main fused GRU: persistent per-block scan, HMMA core.
// Round 9: 2-pass fp16 split (A = hi + lo, B = fp16): -33% MMA count.
// ---------------------------------------------------------------------------
__global__ void __launch_bounds__(NTH, 2)
gru_hmma_kernel(const float* __restrict__ x,
                const float* __restrict__ bias,
                const float* __restrict__ dw,
                const float* __restrict__ db,
                float* __restrict__ out)
{
    __shared__ uint4 Ah[2][NKT][2][32];
    __shared__ float hs[TILE_B][HID + 1];

    const int tid  = threadIdx.x;
    const int wid  = tid >> 5;
    const int lane = tid & 31;
    const int gid  = lane >> 2;
    const int tg   = lane & 3;
    const int b0   = blockIdx.x * TILE_B;
    const float* xg = x + (size_t)b0 * (TSTEPS * FEAT);

    for (int i = tid; i < 2 * NKT * 2 * 32; i += NTH)
        ((uint4*)Ah)[i] = make_uint4(0, 0, 0, 0);

    // bias -> accumulator-init registers: bp[u][e], u = g*2+nt
    float bp[8][2];
#pragma unroll
    for (int g = 0; g < 4; g++)
#pragma unroll
        for (int nt = 0; nt < 2; nt++) {
            int jl = 16 * wid + 8 * nt + 2 * tg;
#pragma unroll
            for (int e = 0; e < 2; e++) {
                int j = jl + e;
                float v;
                if      (g == 0) v = bias[j]       + bias[G3 + j];
                else if (g == 1) v = bias[128 + j] + bias[G3 + 128 + j];
                else if (g == 2) v = bias[G3 + 256 + j];
                else             v = bias[256 + j];
                bp[g * 2 + nt][e] = v;
            }
        }
    __syncthreads();

    auto stage_x = [&](int t) {
#pragma unroll
        for (int i = 0; i < 2; i++) {
            int s   = tid * 2 + i;
            int r   = s & 3;
            int ln  = (s >> 2) & 31;
            int mt  = (s >> 7) & 1;
            int kt8 = s >> 8;
            int gd = ln >> 2, tgg = ln & 3;
            int row = mt * 16 + gd + 8 * (r & 1);
            int kl  = kt8 * 16 + tgg * 2 + 8 * (r >> 1);
            float v0 = 0.0f, v1 = 0.0f;
            if (kl < FEAT) {
                const float* p = xg + (size_t)row * (TSTEPS * FEAT) + t * FEAT + kl;
                v0 = p[0];
                if (kl + 1 < FEAT) v1 = p[1];
            }
            __half h0 = __float2half_rn(v0), h1 = __float2half_rn(v1);
            float l0 = v0 - __half2float(h0), l1 = v1 - __half2float(h1);
            ((uint32_t*)&Ah[0][8 + kt8][mt][ln])[r] =
                (uint32_t)(*(unsigned short*)&h0) | ((uint32_t)(*(unsigned short*)&h1) << 16);
            ((uint32_t*)&Ah[1][8 + kt8][mt][ln])[r] = pack_h2(l0, l1);
        }
    };
    stage_x(0);
    __syncthreads();

    float acc[2][8][4];

    for (int t = 0; t < TSTEPS; t++) {
#pragma unroll
        for (int mt = 0; mt < 2; mt++)
#pragma unroll
            for (int u = 0; u < 8; u++) {
                acc[mt][u][0] = bp[u][0]; acc[mt][u][1] = bp[u][1];
                acc[mt][u][2] = bp[u][0]; acc[mt][u][3] = bp[u][1];
            }

        // ---- HMMA mainloop: 2-pass (Ahi*B + Alo*B), pass-major order ----
#pragma unroll
        for (int kt = 0; kt < NKT; kt++) {
            const uint4 Ah0 = Ah[0][kt][0][lane];
            const uint4 Ah1 = Ah[0][kt][1][lane];
            const uint4 Al0 = Ah[1][kt][0][lane];
            const uint4 Al1 = Ah[1][kt][1][lane];
            // active gate groups: kt<8 -> {z, r, rh}; kt>=8 -> {z, r, xh}
            const int g2 = (kt < 8) ? 2 : 3;
            const int gs[3] = {0, 1, g2};

            uint2 Bh[3][2];
#pragma unroll
            for (int gi = 0; gi < 3; gi++) {
                const int base = (((wid * NKT + kt) * 4 + gs[gi]) * 2) * 32 + lane;
                Bh[gi][0] = __ldg(&gB_hi[base]);
                Bh[gi][1] = __ldg(&gB_hi[base + 32]);
            }

            // pass 1: Ahi * B  (12 independent accumulators)
#pragma unroll
            for (int gi = 0; gi < 3; gi++)
#pragma unroll
                for (int nt = 0; nt < 2; nt++) {
                    const int u = gs[gi] * 2 + nt;
                    mma16816(acc[0][u], Ah0, Bh[gi][nt].x, Bh[gi][nt].y);
                    mma16816(acc[1][u], Ah1, Bh[gi][nt].x, Bh[gi][nt].y);
                }
            // pass 2: Alo * B
#pragma unroll
            for (int gi = 0; gi < 3; gi++)
#pragma unroll
                for (int nt = 0; nt < 2; nt++) {
                    const int u = gs[gi] * 2 + nt;
                    mma16816(acc[0][u], Al0, Bh[gi][nt].x, Bh[gi][nt].y);
                    mma16816(acc[1][u], Al1, Bh[gi][nt].x, Bh[gi][nt].y);
                }
        }
        __syncthreads();   // all warps done reading A frags

        // ---- epilogue: gates in-register; commit new h frags (kt = wid) ----
#pragma unroll
        for (int mt = 0; mt < 2; mt++) {
            uint4 Hh = Ah[0][wid][mt][lane];
            uint4 Hl = Ah[1][wid][mt][lane];
            const uint32_t hh_[4] = {Hh.x, Hh.y, Hh.z, Hh.w};
            const uint32_t hl_[4] = {Hl.x, Hl.y, Hl.z, Hl.w};
            uint32_t nh[4], nl[4];
#pragma unroll
            for (int r = 0; r < 4; r++) {
                const int nt = r >> 1;
                const int ci = (r & 1) * 2;
                float2 oh = unpack_h2(hh_[r]);
                float2 ol = unpack_h2(hl_[r]);
                float hold[2] = {oh.x + ol.x, oh.y + ol.y};
                float hnew[2];
#pragma unroll
                for (int e = 0; e < 2; e++) {
                    float z  = sig_(acc[mt][0 + nt][ci + e]);
                    float rr = sig_(acc[mt][2 + nt][ci + e]);
                    float hc = tanh_(acc[mt][6 + nt][ci + e] + rr * acc[mt][4 + nt][ci + e]);
                    hnew[e] = z * hold[e] + (1.0f - z) * hc;
                    if (t == TSTEPS - 1) {
                        int row = mt * 16 + gid + 8 * (r & 1);
                        int j   = 16 * wid + 8 * nt + 2 * tg + e;
                        hs[row][j] = hnew[e];
                    }
                }
                __half p0 = __float2half_rn(hnew[0]), p1 = __float2half_rn(hnew[1]);
                float r0 = hnew[0] - __half2float(p0), r1 = hnew[1] - __half2float(p1);
                nh[r] = (uint32_t)(*(unsigned short*)&p0) |
                        ((uint32_t)(*(unsigned short*)&p1) << 16);
                nl[r] = pack_h2(r0, r1);
            }
            Ah[0][wid][mt][lane] = make_uint4(nh[0], nh[1], nh[2], nh[3]);
            Ah[1][wid][mt][lane] = make_uint4(nl[0], nl[1], nl[2], nl[3]);
        }

        if (t < TSTEPS - 1) stage_x(t + 1);
        __syncthreads();   // new A frags visible to all warps
    }

    // ---- dense + softmax ----
    if (tid < TILE_B) {
        const int row = tid;
        float lg[NCLS];
#pragma unroll
        for (int c = 0; c < NCLS; c++) lg[c] = db[c];
        for (int j = 0; j < HID; j++) {
            float hv = hs[row][j];
#pragma unroll
            for (int c = 0; c < NCLS; c++) lg[c] = fmaf(hv, dw[j * NCLS + c], lg[c]);
        }
        float m = lg[0];
#pragma unroll
        for (int c = 1; c < NCLS; c++) m = fmaxf(m, lg[c]);
        float s = 0.0f;
#pragma unroll
        for (int c = 0; c < NCLS; c++) { lg[c] = expf(lg[c] - m); s += lg[c]; }
        float inv = 1.0f / s;
#pragma unroll
        for (int c = 0; c < NCLS; c++)
            out[(size_t)(b0 + row) * NCLS + c] = lg[c] * inv;
    }
}

extern "C" void kernel_launch(void* const* d_in, const int* in_sizes, int n_in,
                              void* d_out, int out_size) {
    const float* x    = (const float*)d_in[0];
    const float* Wk   = (const float*)d_in[1];
    const float* Rk   = (const float*)d_in[2];
    const float* bias = (const float*)d_in[3];
    const float* dw   = (const float*)d_in[4];
    const float* db   = (const float*)d_in[5];
    float* out = (float*)d_out;

    prep_B<<<(NBFR + 255) / 256, 256>>>(Rk, Wk);
    gru_hmma_kernel<<<NBLK, NTH>>>(x, bias, dw, db, out);
}

// round 10
// speedup vs baseline: 1.4218x; 1.1084x over previous
#include <cuda_runtime.h>
#include <cuda_fp16.h>
#include <cstdint>
#include <math.h>

#define BATCH   16384
#define TSTEPS  28
#define FEAT    28
#define HID     128
#define G3      384
#define NCLS    10

#define TILE_B  32
#define NTH     256
#define NKT     10          // K chunks of 16: kt 0..7 = h (k=j), kt 8,9 = x
#define NBLK    (BATCH / TILE_B)
#define NBFR    (8 * NKT * 4 * 2 * 32)

// B operand (fp16), fragment-linear:
// index [w(8)][kt(10)][g(4)][nt(2)][lane(32)] : uint2 {b0, b1}
__device__ __align__(16) uint2 gB_hi[NBFR];

__device__ __forceinline__ uint32_t pack_h2(float a, float b) {
    __half2 p = __floats2half2_rn(a, b);
    return *reinterpret_cast<uint32_t*>(&p);
}
__device__ __forceinline__ float2 unpack_h2(uint32_t u) {
    __half2 p = *reinterpret_cast<__half2*>(&u);
    return __half22float2(p);
}

__device__ __forceinline__ void mma16816(float* c, const uint4& a,
                                         uint32_t b0, uint32_t b1) {
    asm volatile(
        "mma.sync.aligned.m16n8k16.row.col.f32.f16.f16.f32 "
        "{%0,%1,%2,%3}, {%4,%5,%6,%7}, {%8,%9}, {%0,%1,%2,%3};"
        : "+f"(c[0]), "+f"(c[1]), "+f"(c[2]), "+f"(c[3])
        : "r"(a.x), "r"(a.y), "r"(a.z), "r"(a.w), "r"(b0), "r"(b1));
}

__device__ __forceinline__ float sig_(float v) { return 1.0f / (1.0f + __expf(-v)); }
__device__ __forceinline__ float tanh_(float v) {
    float t = __expf(-2.0f * fabsf(v));
    float r = (1.0f - t) / (1.0f + t);
    return v < 0.0f ? -r : r;
}

// ---------------------------------------------------------------------------
// Prep: weights -> fragment-linear fp16 (round-to-nearest).
// g: 0=z(col j), 1=r(col 128+j), 2=rh(col 256+j, R rows), 3=xh(col 256+j, W rows)
// ---------------------------------------------------------------------------
__global__ void prep_B(const float* __restrict__ Rk, const float* __restrict__ Wk) {
    int idx = blockIdx.x * blockDim.x + threadIdx.x;
    if (idx >= NBFR) return;
    int lane = idx & 31;
    int nt   = (idx >> 5) & 1;
    int g    = (idx >> 6) & 3;
    int kt   = (idx >> 8) % NKT;
    int w    = (idx >> 8) / NKT;
    int gid  = lane >> 2, tg = lane & 3;

    int jloc = 16 * w + 8 * nt + gid;
    int wcol = (g == 0) ? jloc : (g == 1 ? 128 + jloc : 256 + jloc);
    int k0   = kt * 16 + tg * 2;

    float v[4];
#pragma unroll
    for (int i = 0; i < 4; i++) {
        int k = k0 + (i >> 1) * 8 + (i & 1);
        float val = 0.0f;
        if (k < HID) { if (g != 3) val = Rk[k * G3 + wcol]; }
        else { int f = k - HID; if (f < FEAT && g != 2) val = Wk[f * G3 + wcol]; }
        v[i] = val;
    }
    __half h[4];
#pragma unroll
    for (int i = 0; i < 4; i++) h[i] = __float2half_rn(v[i]);
    uint2 fh;
    fh.x = (uint32_t)(*(unsigned short*)&h[0]) | ((uint32_t)(*(unsigned short*)&h[1]) << 16);
    fh.y = (uint32_t)(*(unsigned short*)&h[2]) | ((uint32_t)(*(unsigned short*)&h[3]) << 16);
    gB_hi[idx] = fh;
}

// ---------------------------------------------------------------------------
// Main fused GRU: persistent per-block scan, HMMA core.
// Round 10: lo-pass only for tanh path; x prefetch; compact t-loop.
// ---------------------------------------------------------------------------
__global__ void __launch_bounds__(NTH, 2)
gru_hmma_kernel(const float* __restrict__ x,
                const float* __restrict__ bias,
                const float* __restrict__ dw,
                const float* __restrict__ db,
                float* __restrict__ out)
{
    __shared__ uint4 Ah[2][NKT][2][32];
    __shared__ float hs[TILE_B][HID + 1];

    const int tid  = threadIdx.x;
    const int wid  = tid >> 5;
    const int lane = tid & 31;
    const int gid  = lane >> 2;
    const int tg   = lane & 3;
    const int b0   = blockIdx.x * TILE_B;
    const float* xg = x + (size_t)b0 * (TSTEPS * FEAT);

    for (int i = tid; i < 2 * NKT * 2 * 32; i += NTH)
        ((uint4*)Ah)[i] = make_uint4(0, 0, 0, 0);

    // bias -> accumulator-init registers: bp[u][e], u = g*2+nt
    float bp[8][2];
#pragma unroll
    for (int g = 0; g < 4; g++)
#pragma unroll
        for (int nt = 0; nt < 2; nt++) {
            int jl = 16 * wid + 8 * nt + 2 * tg;
#pragma unroll
            for (int e = 0; e < 2; e++) {
                int j = jl + e;
                float v;
                if      (g == 0) v = bias[j]       + bias[G3 + j];
                else if (g == 1) v = bias[128 + j] + bias[G3 + 128 + j];
                else if (g == 2) v = bias[G3 + 256 + j];
                else             v = bias[256 + j];
                bp[g * 2 + nt][e] = v;
            }
        }

    // per-thread x staging geometry (2 slots/thread)
    int xrow[2], xkl[2], xmt[2], xkt8[2], xr[2], xln[2];
#pragma unroll
    for (int i = 0; i < 2; i++) {
        int s   = tid * 2 + i;
        xr[i]   = s & 3;
        xln[i]  = (s >> 2) & 31;
        xmt[i]  = (s >> 7) & 1;
        xkt8[i] = s >> 8;
        int gd = xln[i] >> 2, tgg = xln[i] & 3;
        xrow[i] = xmt[i] * 16 + gd + 8 * (xr[i] & 1);
        xkl[i]  = xkt8[i] * 16 + tgg * 2 + 8 * (xr[i] >> 1);
    }

    auto ld_x = [&](int t, float* v0, float* v1) {
#pragma unroll
        for (int i = 0; i < 2; i++) {
            v0[i] = 0.0f; v1[i] = 0.0f;
            if (xkl[i] < FEAT) {
                const float* p = xg + (size_t)xrow[i] * (TSTEPS * FEAT) + t * FEAT + xkl[i];
                v0[i] = __ldg(p);
                if (xkl[i] + 1 < FEAT) v1[i] = __ldg(p + 1);
            }
        }
    };
    auto st_x = [&](const float* v0, const float* v1) {
#pragma unroll
        for (int i = 0; i < 2; i++) {
            __half h0 = __float2half_rn(v0[i]), h1 = __float2half_rn(v1[i]);
            float l0 = v0[i] - __half2float(h0), l1 = v1[i] - __half2float(h1);
            ((uint32_t*)&Ah[0][8 + xkt8[i]][xmt[i]][xln[i]])[xr[i]] =
                (uint32_t)(*(unsigned short*)&h0) | ((uint32_t)(*(unsigned short*)&h1) << 16);
            ((uint32_t*)&Ah[1][8 + xkt8[i]][xmt[i]][xln[i]])[xr[i]] = pack_h2(l0, l1);
        }
    };

    {   // stage x(0)
        float v0[2], v1[2];
        ld_x(0, v0, v1);
        st_x(v0, v1);
    }
    __syncthreads();

    float acc[2][8][4];

#pragma unroll 1
    for (int t = 0; t < TSTEPS; t++) {
        // prefetch x(t+1) into registers (latency hidden behind mainloop MMAs)
        float pv0[2], pv1[2];
        if (t < TSTEPS - 1) ld_x(t + 1, pv0, pv1);

#pragma unroll
        for (int mt = 0; mt < 2; mt++)
#pragma unroll
            for (int u = 0; u < 8; u++) {
                acc[mt][u][0] = bp[u][0]; acc[mt][u][1] = bp[u][1];
                acc[mt][u][2] = bp[u][0]; acc[mt][u][3] = bp[u][1];
            }

        // ---- HMMA mainloop ----
#pragma unroll
        for (int kt = 0; kt < NKT; kt++) {
            const uint4 Ah0 = Ah[0][kt][0][lane];
            const uint4 Ah1 = Ah[0][kt][1][lane];
            const uint4 Al0 = Ah[1][kt][0][lane];
            const uint4 Al1 = Ah[1][kt][1][lane];
            // active gate groups: kt<8 -> {z, r, rh}; kt>=8 -> {z, r, xh}
            const int g2 = (kt < 8) ? 2 : 3;
            const int gs[3] = {0, 1, g2};

            uint2 Bh[3][2];
#pragma unroll
            for (int gi = 0; gi < 3; gi++) {
                const int base = (((wid * NKT + kt) * 4 + gs[gi]) * 2) * 32 + lane;
                Bh[gi][0] = __ldg(&gB_hi[base]);
                Bh[gi][1] = __ldg(&gB_hi[base + 32]);
            }

            // pass 1: Ahi * B for all gates (12 independent accumulators)
#pragma unroll
            for (int gi = 0; gi < 3; gi++)
#pragma unroll
                for (int nt = 0; nt < 2; nt++) {
                    const int u = gs[gi] * 2 + nt;
                    mma16816(acc[0][u], Ah0, Bh[gi][nt].x, Bh[gi][nt].y);
                    mma16816(acc[1][u], Ah1, Bh[gi][nt].x, Bh[gi][nt].y);
                }
            // pass 2: Alo * B only for the tanh path (rh / xh)
#pragma unroll
            for (int nt = 0; nt < 2; nt++) {
                const int u = g2 * 2 + nt;
                mma16816(acc[0][u], Al0, Bh[2][nt].x, Bh[2][nt].y);
                mma16816(acc[1][u], Al1, Bh[2][nt].x, Bh[2][nt].y);
            }
        }
        __syncthreads();   // all warps done reading A frags

        // ---- epilogue: gates in-register; commit new h frags (kt = wid) ----
#pragma unroll
        for (int mt = 0; mt < 2; mt++) {
            uint4 Hh = Ah[0][wid][mt][lane];
            uint4 Hl = Ah[1][wid][mt][lane];
            const uint32_t hh_[4] = {Hh.x, Hh.y, Hh.z, Hh.w};
            const uint32_t hl_[4] = {Hl.x, Hl.y, Hl.z, Hl.w};
            uint32_t nh[4], nl[4];
#pragma unroll
            for (int r = 0; r < 4; r++) {
                const int nt = r >> 1;
                const int ci = (r & 1) * 2;
                float2 oh = unpack_h2(hh_[r]);
                float2 ol = unpack_h2(hl_[r]);
                float hold[2] = {oh.x + ol.x, oh.y + ol.y};
                float hnew[2];
#pragma unroll
                for (int e = 0; e < 2; e++) {
                    float z  = sig_(acc[mt][0 + nt][ci + e]);
                    float rr = sig_(acc[mt][2 + nt][ci + e]);
                    float hc = tanh_(acc[mt][6 + nt][ci + e] + rr * acc[mt][4 + nt][ci + e]);
                    hnew[e] = z * hold[e] + (1.0f - z) * hc;
                    if (t == TSTEPS - 1) {
                        int row = mt * 16 + gid + 8 * (r & 1);
                        int j   = 16 * wid + 8 * nt + 2 * tg + e;
                        hs[row][j] = hnew[e];
                    }
                }
                __half p0 = __float2half_rn(hnew[0]), p1 = __float2half_rn(hnew[1]);
                float r0 = hnew[0] - __half2float(p0), r1 = hnew[1] - __half2float(p1);
                nh[r] = (uint32_t)(*(unsigned short*)&p0) |
                        ((uint32_t)(*(unsigned short*)&p1) << 16);
                nl[r] = pack_h2(r0, r1);
            }
            Ah[0][wid][mt][lane] = make_uint4(nh[0], nh[1], nh[2], nh[3]);
            Ah[1][wid][mt][lane] = make_uint4(nl[0], nl[1], nl[2], nl[3]);
        }

        if (t < TSTEPS - 1) st_x(pv0, pv1);
        __syncthreads();   // new A frags visible to all warps
    }

    // ---- dense + softmax ----
    if (tid < TILE_B) {
        const int row = tid;
        float lg[NCLS];
#pragma unroll
        for (int c = 0; c < NCLS; c++) lg[c] = db[c];
        for (int j = 0; j < HID; j++) {
            float hv = hs[row][j];
#pragma unroll
            for (int c = 0; c < NCLS; c++) lg[c] = fmaf(hv, dw[j * NCLS + c], lg[c]);
        }
        float m = lg[0];
#pragma unroll
        for (int c = 1; c < NCLS; c++) m = fmaxf(m, lg[c]);
        float s = 0.0f;
#pragma unroll
        for (int c = 0; c < NCLS; c++) { lg[c] = expf(lg[c] - m); s += lg[c]; }
        float inv = 1.0f / s;
#pragma unroll
        for (int c = 0; c < NCLS; c++)
            out[(size_t)(b0 + row) * NCLS + c] = lg[c] * inv;
    }
}

extern "C" void kernel_launch(void* const* d_in, const int* in_sizes, int n_in,
                              void* d_out, int out_size) {
    const float* x    = (const float*)d_in[0];
    const float* Wk   = (const float*)d_in[1];
    const float* Rk   = (const float*)d_in[2];
    const float* bias = (const float*)d_in[3];
    const float* dw   = (const float*)d_in[4];
    const float* db   = (const float*)d_in[5];
    float* out = (float*)d_out;

    prep_B<<<(NBFR + 255) / 256, 256>>>(Rk, Wk);
    gru_hmma_kernel<<<NBLK, NTH>>>(x, bias, dw, db, out);
}

// round 11
// speedup vs baseline: 1.8506x; 1.3016x over previous
#include <cuda_runtime.h>
#include <cuda_fp16.h>
#include <cstdint>
#include <math.h>

#define BATCH   16384
#define TSTEPS  28
#define FEAT    28
#define HID     128
#define G3      384
#define NCLS    10

#define TILE_B  32
#define NTH     256
#define NKT     10          // K chunks of 16: kt 0..7 = h (k=j), kt 8,9 = x
#define NBLK    (BATCH / TILE_B)
#define NBFR    (8 * NKT * 4 * 2 * 32)

// B operand (fp16), fragment-linear:
// index [w(8)][kt(10)][g(4)][nt(2)][lane(32)] : uint2 {b0, b1}
__device__ __align__(16) uint2 gB_hi[NBFR];

__device__ __forceinline__ uint32_t pack_h2(float a, float b) {
    __half2 p = __floats2half2_rn(a, b);
    return *reinterpret_cast<uint32_t*>(&p);
}
__device__ __forceinline__ float2 unpack_h2(uint32_t u) {
    __half2 p = *reinterpret_cast<__half2*>(&u);
    return __half22float2(p);
}

__device__ __forceinline__ void mma16816(float* c, const uint4& a,
                                         uint32_t b0, uint32_t b1) {
    asm volatile(
        "mma.sync.aligned.m16n8k16.row.col.f32.f16.f16.f32 "
        "{%0,%1,%2,%3}, {%4,%5,%6,%7}, {%8,%9}, {%0,%1,%2,%3};"
        : "+f"(c[0]), "+f"(c[1]), "+f"(c[2]), "+f"(c[3])
        : "r"(a.x), "r"(a.y), "r"(a.z), "r"(a.w), "r"(b0), "r"(b1));
}

// fast sigmoid/tanh: MUFU.EX2 + MUFU.RCP (2 ulp), no IEEE division
__device__ __forceinline__ float sig_(float v) {
    return __fdividef(1.0f, 1.0f + __expf(-v));
}
__device__ __forceinline__ float tanh_(float v) {
    float t = __expf(-2.0f * fabsf(v));
    float r = __fdividef(1.0f - t, 1.0f + t);
    return v < 0.0f ? -r : r;
}

// ---------------------------------------------------------------------------
// Prep: weights -> fragment-linear fp16 (round-to-nearest).
// g: 0=z(col j), 1=r(col 128+j), 2=rh(col 256+j, R rows), 3=xh(col 256+j, W rows)
// ---------------------------------------------------------------------------
__global__ void prep_B(const float* __restrict__ Rk, const float* __restrict__ Wk) {
    int idx = blockIdx.x * blockDim.x + threadIdx.x;
    if (idx >= NBFR) return;
    int lane = idx & 31;
    int nt   = (idx >> 5) & 1;
    int g    = (idx >> 6) & 3;
    int kt   = (idx >> 8) % NKT;
    int w    = (idx >> 8) / NKT;
    int gid  = lane >> 2, tg = lane & 3;

    int jloc = 16 * w + 8 * nt + gid;
    int wcol = (g == 0) ? jloc : (g == 1 ? 128 + jloc : 256 + jloc);
    int k0   = kt * 16 + tg * 2;

    float v[4];
#pragma unroll
    for (int i = 0; i < 4; i++) {
        int k = k0 + (i >> 1) * 8 + (i & 1);
        float val = 0.0f;
        if (k < HID) { if (g != 3) val = Rk[k * G3 + wcol]; }
        else { int f = k - HID; if (f < FEAT && g != 2) val = Wk[f * G3 + wcol]; }
        v[i] = val;
    }
    __half h[4];
#pragma unroll
    for (int i = 0; i < 4; i++) h[i] = __float2half_rn(v[i]);
    uint2 fh;
    fh.x = (uint32_t)(*(unsigned short*)&h[0]) | ((uint32_t)(*(unsigned short*)&h[1]) << 16);
    fh.y = (uint32_t)(*(unsigned short*)&h[2]) | ((uint32_t)(*(unsigned short*)&h[3]) << 16);
    gB_hi[idx] = fh;
}

// ---------------------------------------------------------------------------
// Main fused GRU: persistent per-block scan, HMMA core.
// Round 11: double-buffered A frags (1 barrier/step, epilogue overlap)
//           + fast-division gates.
// ---------------------------------------------------------------------------
__global__ void __launch_bounds__(NTH, 2)
gru_hmma_kernel(const float* __restrict__ x,
                const float* __restrict__ bias,
                const float* __restrict__ dw,
                const float* __restrict__ db,
                float* __restrict__ out)
{
    __shared__ uint4 Ah[2][2][NKT][2][32];   // [buf][split][kt][mt][lane]
    __shared__ float hs[TILE_B][HID + 1];

    const int tid  = threadIdx.x;
    const int wid  = tid >> 5;
    const int lane = tid & 31;
    const int gid  = lane >> 2;
    const int tg   = lane & 3;
    const int b0   = blockIdx.x * TILE_B;
    const float* xg = x + (size_t)b0 * (TSTEPS * FEAT);

    // zero buffer 0 (h region must start as 0; buf 1 fully written in step 0)
    for (int i = tid; i < 2 * NKT * 2 * 32; i += NTH)
        ((uint4*)Ah[0])[i] = make_uint4(0, 0, 0, 0);

    // bias -> accumulator-init registers: bp[u][e], u = g*2+nt
    float bp[8][2];
#pragma unroll
    for (int g = 0; g < 4; g++)
#pragma unroll
        for (int nt = 0; nt < 2; nt++) {
            int jl = 16 * wid + 8 * nt + 2 * tg;
#pragma unroll
            for (int e = 0; e < 2; e++) {
                int j = jl + e;
                float v;
                if      (g == 0) v = bias[j]       + bias[G3 + j];
                else if (g == 1) v = bias[128 + j] + bias[G3 + 128 + j];
                else if (g == 2) v = bias[G3 + 256 + j];
                else             v = bias[256 + j];
                bp[g * 2 + nt][e] = v;
            }
        }

    // per-thread x staging geometry (2 slots/thread)
    int xrow[2], xkl[2], xmt[2], xkt8[2], xr[2], xln[2];
#pragma unroll
    for (int i = 0; i < 2; i++) {
        int s   = tid * 2 + i;
        xr[i]   = s & 3;
        xln[i]  = (s >> 2) & 31;
        xmt[i]  = (s >> 7) & 1;
        xkt8[i] = s >> 8;
        int gd = xln[i] >> 2, tgg = xln[i] & 3;
        xrow[i] = xmt[i] * 16 + gd + 8 * (xr[i] & 1);
        xkl[i]  = xkt8[i] * 16 + tgg * 2 + 8 * (xr[i] >> 1);
    }

    auto ld_x = [&](int t, float* v0, float* v1) {
#pragma unroll
        for (int i = 0; i < 2; i++) {
            v0[i] = 0.0f; v1[i] = 0.0f;
            if (xkl[i] < FEAT) {
                const float* p = xg + (size_t)xrow[i] * (TSTEPS * FEAT) + t * FEAT + xkl[i];
                v0[i] = __ldg(p);
                if (xkl[i] + 1 < FEAT) v1[i] = __ldg(p + 1);
            }
        }
    };
    auto st_x = [&](int buf, const float* v0, const float* v1) {
#pragma unroll
        for (int i = 0; i < 2; i++) {
            __half h0 = __float2half_rn(v0[i]), h1 = __float2half_rn(v1[i]);
            float l0 = v0[i] - __half2float(h0), l1 = v1[i] - __half2float(h1);
            ((uint32_t*)&Ah[buf][0][8 + xkt8[i]][xmt[i]][xln[i]])[xr[i]] =
                (uint32_t)(*(unsigned short*)&h0) | ((uint32_t)(*(unsigned short*)&h1) << 16);
            ((uint32_t*)&Ah[buf][1][8 + xkt8[i]][xmt[i]][xln[i]])[xr[i]] = pack_h2(l0, l1);
        }
    };

    {   // stage x(0) into buffer 0
        float v0[2], v1[2];
        ld_x(0, v0, v1);
        st_x(0, v0, v1);
    }
    __syncthreads();

    float acc[2][8][4];

#pragma unroll 1
    for (int t = 0; t < TSTEPS; t++) {
        const int p = t & 1;         // read buffer
        const int q = p ^ 1;         // write buffer (next step's read)

        // prefetch x(t+1) into registers (latency hidden behind mainloop MMAs)
        float pv0[2], pv1[2];
        if (t < TSTEPS - 1) ld_x(t + 1, pv0, pv1);

#pragma unroll
        for (int mt = 0; mt < 2; mt++)
#pragma unroll
            for (int u = 0; u < 8; u++) {
                acc[mt][u][0] = bp[u][0]; acc[mt][u][1] = bp[u][1];
                acc[mt][u][2] = bp[u][0]; acc[mt][u][3] = bp[u][1];
            }

        // ---- HMMA mainloop (reads buf p) ----
#pragma unroll
        for (int kt = 0; kt < NKT; kt++) {
            const uint4 Ah0 = Ah[p][0][kt][0][lane];
            const uint4 Ah1 = Ah[p][0][kt][1][lane];
            const uint4 Al0 = Ah[p][1][kt][0][lane];
            const uint4 Al1 = Ah[p][1][kt][1][lane];
            // active gate groups: kt<8 -> {z, r, rh}; kt>=8 -> {z, r, xh}
            const int g2 = (kt < 8) ? 2 : 3;
            const int gs[3] = {0, 1, g2};

            uint2 Bh[3][2];
#pragma unroll
            for (int gi = 0; gi < 3; gi++) {
                const int base = (((wid * NKT + kt) * 4 + gs[gi]) * 2) * 32 + lane;
                Bh[gi][0] = __ldg(&gB_hi[base]);
                Bh[gi][1] = __ldg(&gB_hi[base + 32]);
            }

            // pass 1: Ahi * B for all gates (12 independent accumulators)
#pragma unroll
            for (int gi = 0; gi < 3; gi++)
#pragma unroll
                for (int nt = 0; nt < 2; nt++) {
                    const int u = gs[gi] * 2 + nt;
                    mma16816(acc[0][u], Ah0, Bh[gi][nt].x, Bh[gi][nt].y);
                    mma16816(acc[1][u], Ah1, Bh[gi][nt].x, Bh[gi][nt].y);
                }
            // pass 2: Alo * B only for the tanh path (rh / xh)
#pragma unroll
            for (int nt = 0; nt < 2; nt++) {
                const int u = g2 * 2 + nt;
                mma16816(acc[0][u], Al0, Bh[2][nt].x, Bh[2][nt].y);
                mma16816(acc[1][u], Al1, Bh[2][nt].x, Bh[2][nt].y);
            }
        }
        // NO barrier here: epilogue writes go to buf q, mainloop readers use buf p.

        // ---- epilogue: gates in-register; write new h frags to buf q ----
#pragma unroll
        for (int mt = 0; mt < 2; mt++) {
            uint4 Hh = Ah[p][0][wid][mt][lane];
            uint4 Hl = Ah[p][1][wid][mt][lane];
            const uint32_t hh_[4] = {Hh.x, Hh.y, Hh.z, Hh.w};
            const uint32_t hl_[4] = {Hl.x, Hl.y, Hl.z, Hl.w};
            uint32_t nh[4], nl[4];
#pragma unroll
            for (int r = 0; r < 4; r++) {
                const int nt = r >> 1;
                const int ci = (r & 1) * 2;
                float2 oh = unpack_h2(hh_[r]);
                float2 ol = unpack_h2(hl_[r]);
                float hold[2] = {oh.x + ol.x, oh.y + ol.y};
                float hnew[2];
#pragma unroll
                for (int e = 0; e < 2; e++) {
                    float z  = sig_(acc[mt][0 + nt][ci + e]);
                    float rr = sig_(acc[mt][2 + nt][ci + e]);
                    float hc = tanh_(acc[mt][6 + nt][ci + e] + rr * acc[mt][4 + nt][ci + e]);
                    hnew[e] = z * hold[e] + (1.0f - z) * hc;
                    if (t == TSTEPS - 1) {
                        int row = mt * 16 + gid + 8 * (r & 1);
                        int j   = 16 * wid + 8 * nt + 2 * tg + e;
                        hs[row][j] = hnew[e];
                    }
                }
                __half p0 = __float2half_rn(hnew[0]), p1 = __float2half_rn(hnew[1]);
                float r0 = hnew[0] - __half2float(p0), r1 = hnew[1] - __half2float(p1);
                nh[r] = (uint32_t)(*(unsigned short*)&p0) |
                        ((uint32_t)(*(unsigned short*)&p1) << 16);
                nl[r] = pack_h2(r0, r1);
            }
            Ah[q][0][wid][mt][lane] = make_uint4(nh[0], nh[1], nh[2], nh[3]);
            Ah[q][1][wid][mt][lane] = make_uint4(nl[0], nl[1], nl[2], nl[3]);
        }

        if (t < TSTEPS - 1) st_x(q, pv0, pv1);
        __syncthreads();   // buf q complete + all buf p reads done -> next step
    }

    // ---- dense + softmax ----
    if (tid < TILE_B) {
        const int row = tid;
        float lg[NCLS];
#pragma unroll
        for (int c = 0; c < NCLS; c++) lg[c] = db[c];
        for (int j = 0; j < HID; j++) {
            float hv = hs[row][j];
#pragma unroll
            for (int c = 0; c < NCLS; c++) lg[c] = fmaf(hv, dw[j * NCLS + c], lg[c]);
        }
        float m = lg[0];
#pragma unroll
        for (int c = 1; c < NCLS; c++) m = fmaxf(m, lg[c]);
        float s = 0.0f;
#pragma unroll
        for (int c = 0; c < NCLS; c++) { lg[c] = expf(lg[c] - m); s += lg[c]; }
        float inv = 1.0f / s;
#pragma unroll
        for (int c = 0; c < NCLS; c++)
            out[(size_t)(b0 + row) * NCLS + c] = lg[c] * inv;
    }
}

extern "C" void kernel_launch(void* const* d_in, const int* in_sizes, int n_in,
                              void* d_out, int out_size) {
    const float* x    = (const float*)d_in[0];
    const float* Wk   = (const float*)d_in[1];
    const float* Rk   = (const float*)d_in[2];
    const float* bias = (const float*)d_in[3];
    const float* dw   = (const float*)d_in[4];
    const float* db   = (const float*)d_in[5];
    float* out = (float*)d_out;

    prep_B<<<(NBFR + 255) / 256, 256>>>(Rk, Wk);
    gru_hmma_kernel<<<NBLK, NTH>>>(x, bias, dw, db, out);
}

// round 12
// speedup vs baseline: 2.0433x; 1.1042x over previous
#include <cuda_runtime.h>
#include <cuda_fp16.h>
#include <cstdint>
#include <math.h>

#define BATCH   16384
#define TSTEPS  28
#define FEAT    28
#define HID     128
#define G3      384
#define NCLS    10

#define TILE_B  32
#define NTH     256
#define NKT     10          // K chunks of 16: kt 0..7 = h (k=j), kt 8,9 = x
#define NBLK    (BATCH / TILE_B)
#define NBFR    (8 * NKT * 4 * 2 * 32)

// B operand (fp16), fragment-linear:
// index [w(8)][kt(10)][g(4)][nt(2)][lane(32)] : uint2 {b0, b1}
__device__ __align__(16) uint2 gB_hi[NBFR];

__device__ __forceinline__ uint32_t pack_h2(float a, float b) {
    __half2 p = __floats2half2_rn(a, b);
    return *reinterpret_cast<uint32_t*>(&p);
}
__device__ __forceinline__ float2 unpack_h2(uint32_t u) {
    __half2 p = *reinterpret_cast<__half2*>(&u);
    return __half22float2(p);
}

__device__ __forceinline__ void mma16816(float* c, const uint4& a,
                                         uint32_t b0, uint32_t b1) {
    asm volatile(
        "mma.sync.aligned.m16n8k16.row.col.f32.f16.f16.f32 "
        "{%0,%1,%2,%3}, {%4,%5,%6,%7}, {%8,%9}, {%0,%1,%2,%3};"
        : "+f"(c[0]), "+f"(c[1]), "+f"(c[2]), "+f"(c[3])
        : "r"(a.x), "r"(a.y), "r"(a.z), "r"(a.w), "r"(b0), "r"(b1));
}

// HW tanh (sm_75+): 1 MUFU op, rel err ~2^-11
__device__ __forceinline__ float tanh_hw(float v) {
    float r;
    asm("tanh.approx.f32 %0, %1;" : "=f"(r) : "f"(v));
    return r;
}
// sigmoid via tanh identity: 1 MUFU + 2 FMA (was EX2+RCP = 2 MUFU)
__device__ __forceinline__ float sig_(float v) {
    return fmaf(0.5f, tanh_hw(0.5f * v), 0.5f);
}

// ---------------------------------------------------------------------------
// Prep: weights -> fragment-linear fp16 (round-to-nearest).
// g: 0=z(col j), 1=r(col 128+j), 2=rh(col 256+j, R rows), 3=xh(col 256+j, W rows)
// ---------------------------------------------------------------------------
__global__ void prep_B(const float* __restrict__ Rk, const float* __restrict__ Wk) {
    int idx = blockIdx.x * blockDim.x + threadIdx.x;
    if (idx >= NBFR) return;
    int lane = idx & 31;
    int nt   = (idx >> 5) & 1;
    int g    = (idx >> 6) & 3;
    int kt   = (idx >> 8) % NKT;
    int w    = (idx >> 8) / NKT;
    int gid  = lane >> 2, tg = lane & 3;

    int jloc = 16 * w + 8 * nt + gid;
    int wcol = (g == 0) ? jloc : (g == 1 ? 128 + jloc : 256 + jloc);
    int k0   = kt * 16 + tg * 2;

    float v[4];
#pragma unroll
    for (int i = 0; i < 4; i++) {
        int k = k0 + (i >> 1) * 8 + (i & 1);
        float val = 0.0f;
        if (k < HID) { if (g != 3) val = Rk[k * G3 + wcol]; }
        else { int f = k - HID; if (f < FEAT && g != 2) val = Wk[f * G3 + wcol]; }
        v[i] = val;
    }
    __half h[4];
#pragma unroll
    for (int i = 0; i < 4; i++) h[i] = __float2half_rn(v[i]);
    uint2 fh;
    fh.x = (uint32_t)(*(unsigned short*)&h[0]) | ((uint32_t)(*(unsigned short*)&h[1]) << 16);
    fh.y = (uint32_t)(*(unsigned short*)&h[2]) | ((uint32_t)(*(unsigned short*)&h[3]) << 16);
    gB_hi[idx] = fh;
}

// ---------------------------------------------------------------------------
// Main fused GRU: persistent per-block scan, HMMA core.
// Round 12: HW tanh activations (3 MUFU/elem instead of 6).
// ---------------------------------------------------------------------------
__global__ void __launch_bounds__(NTH, 2)
gru_hmma_kernel(const float* __restrict__ x,
                const float* __restrict__ bias,
                const float* __restrict__ dw,
                const float* __restrict__ db,
                float* __restrict__ out)
{
    __shared__ uint4 Ah[2][2][NKT][2][32];   // [buf][split][kt][mt][lane]
    __shared__ float hs[TILE_B][HID + 1];

    const int tid  = threadIdx.x;
    const int wid  = tid >> 5;
    const int lane = tid & 31;
    const int gid  = lane >> 2;
    const int tg   = lane & 3;
    const int b0   = blockIdx.x * TILE_B;
    const float* xg = x + (size_t)b0 * (TSTEPS * FEAT);

    // zero buffer 0 (h region must start as 0; buf 1 fully written in step 0)
    for (int i = tid; i < 2 * NKT * 2 * 32; i += NTH)
        ((uint4*)Ah[0])[i] = make_uint4(0, 0, 0, 0);

    // bias -> accumulator-init registers: bp[u][e], u = g*2+nt
    float bp[8][2];
#pragma unroll
    for (int g = 0; g < 4; g++)
#pragma unroll
        for (int nt = 0; nt < 2; nt++) {
            int jl = 16 * wid + 8 * nt + 2 * tg;
#pragma unroll
            for (int e = 0; e < 2; e++) {
                int j = jl + e;
                float v;
                if      (g == 0) v = bias[j]       + bias[G3 + j];
                else if (g == 1) v = bias[128 + j] + bias[G3 + 128 + j];
                else if (g == 2) v = bias[G3 + 256 + j];
                else             v = bias[256 + j];
                bp[g * 2 + nt][e] = v;
            }
        }

    // per-thread x staging geometry (2 slots/thread)
    int xrow[2], xkl[2], xmt[2], xkt8[2], xr[2], xln[2];
#pragma unroll
    for (int i = 0; i < 2; i++) {
        int s   = tid * 2 + i;
        xr[i]   = s & 3;
        xln[i]  = (s >> 2) & 31;
        xmt[i]  = (s >> 7) & 1;
        xkt8[i] = s >> 8;
        int gd = xln[i] >> 2, tgg = xln[i] & 3;
        xrow[i] = xmt[i] * 16 + gd + 8 * (xr[i] & 1);
        xkl[i]  = xkt8[i] * 16 + tgg * 2 + 8 * (xr[i] >> 1);
    }

    auto ld_x = [&](int t, float* v0, float* v1) {
#pragma unroll
        for (int i = 0; i < 2; i++) {
            v0[i] = 0.0f; v1[i] = 0.0f;
            if (xkl[i] < FEAT) {
                const float* p = xg + (size_t)xrow[i] * (TSTEPS * FEAT) + t * FEAT + xkl[i];
                v0[i] = __ldg(p);
                if (xkl[i] + 1 < FEAT) v1[i] = __ldg(p + 1);
            }
        }
    };
    auto st_x = [&](int buf, const float* v0, const float* v1) {
#pragma unroll
        for (int i = 0; i < 2; i++) {
            __half h0 = __float2half_rn(v0[i]), h1 = __float2half_rn(v1[i]);
            float l0 = v0[i] - __half2float(h0), l1 = v1[i] - __half2float(h1);
            ((uint32_t*)&Ah[buf][0][8 + xkt8[i]][xmt[i]][xln[i]])[xr[i]] =
                (uint32_t)(*(unsigned short*)&h0) | ((uint32_t)(*(unsigned short*)&h1) << 16);
            ((uint32_t*)&Ah[buf][1][8 + xkt8[i]][xmt[i]][xln[i]])[xr[i]] = pack_h2(l0, l1);
        }
    };

    {   // stage x(0) into buffer 0
        float v0[2], v1[2];
        ld_x(0, v0, v1);
        st_x(0, v0, v1);
    }
    __syncthreads();

    float acc[2][8][4];

#pragma unroll 1
    for (int t = 0; t < TSTEPS; t++) {
        const int p = t & 1;         // read buffer
        const int q = p ^ 1;         // write buffer (next step's read)

        // prefetch x(t+1) into registers (latency hidden behind mainloop MMAs)
        float pv0[2], pv1[2];
        if (t < TSTEPS - 1) ld_x(t + 1, pv0, pv1);

#pragma unroll
        for (int mt = 0; mt < 2; mt++)
#pragma unroll
            for (int u = 0; u < 8; u++) {
                acc[mt][u][0] = bp[u][0]; acc[mt][u][1] = bp[u][1];
                acc[mt][u][2] = bp[u][0]; acc[mt][u][3] = bp[u][1];
            }

        // ---- HMMA mainloop (reads buf p) ----
#pragma unroll
        for (int kt = 0; kt < NKT; kt++) {
            const uint4 Ah0 = Ah[p][0][kt][0][lane];
            const uint4 Ah1 = Ah[p][0][kt][1][lane];
            const uint4 Al0 = Ah[p][1][kt][0][lane];
            const uint4 Al1 = Ah[p][1][kt][1][lane];
            // active gate groups: kt<8 -> {z, r, rh}; kt>=8 -> {z, r, xh}
            const int g2 = (kt < 8) ? 2 : 3;
            const int gs[3] = {0, 1, g2};

            uint2 Bh[3][2];
#pragma unroll
            for (int gi = 0; gi < 3; gi++) {
                const int base = (((wid * NKT + kt) * 4 + gs[gi]) * 2) * 32 + lane;
                Bh[gi][0] = __ldg(&gB_hi[base]);
                Bh[gi][1] = __ldg(&gB_hi[base + 32]);
            }

            // pass 1: Ahi * B for all gates (12 independent accumulators)
#pragma unroll
            for (int gi = 0; gi < 3; gi++)
#pragma unroll
                for (int nt = 0; nt < 2; nt++) {
                    const int u = gs[gi] * 2 + nt;
                    mma16816(acc[0][u], Ah0, Bh[gi][nt].x, Bh[gi][nt].y);
                    mma16816(acc[1][u], Ah1, Bh[gi][nt].x, Bh[gi][nt].y);
                }
            // pass 2: Alo * B only for the tanh path (rh / xh)
#pragma unroll
            for (int nt = 0; nt < 2; nt++) {
                const int u = g2 * 2 + nt;
                mma16816(acc[0][u], Al0, Bh[2][nt].x, Bh[2][nt].y);
                mma16816(acc[1][u], Al1, Bh[2][nt].x, Bh[2][nt].y);
            }
        }
        // NO barrier here: epilogue writes go to buf q, mainloop readers use buf p.

        // ---- epilogue: gates in-register; write new h frags to buf q ----
#pragma unroll
        for (int mt = 0; mt < 2; mt++) {
            uint4 Hh = Ah[p][0][wid][mt][lane];
            uint4 Hl = Ah[p][1][wid][mt][lane];
            const uint32_t hh_[4] = {Hh.x, Hh.y, Hh.z, Hh.w};
            const uint32_t hl_[4] = {Hl.x, Hl.y, Hl.z, Hl.w};
            uint32_t nh[4], nl[4];
#pragma unroll
            for (int r = 0; r < 4; r++) {
                const int nt = r >> 1;
                const int ci = (r & 1) * 2;
                float2 oh = unpack_h2(hh_[r]);
                float2 ol = unpack_h2(hl_[r]);
                float hold[2] = {oh.x + ol.x, oh.y + ol.y};
                float hnew[2];
#pragma unroll
                for (int e = 0; e < 2; e++) {
                    float z  = sig_(acc[mt][0 + nt][ci + e]);
                    float rr = sig_(acc[mt][2 + nt][ci + e]);
                    float hc = tanh_hw(acc[mt][6 + nt][ci + e] + rr * acc[mt][4 + nt][ci + e]);
                    hnew[e] = hc + z * (hold[e] - hc);
                    if (t == TSTEPS - 1) {
                        int row = mt * 16 + gid + 8 * (r & 1);
                        int j   = 16 * wid + 8 * nt + 2 * tg + e;
                        hs[row][j] = hnew[e];
                    }
                }
                __half p0 = __float2half_rn(hnew[0]), p1 = __float2half_rn(hnew[1]);
                float r0 = hnew[0] - __half2float(p0), r1 = hnew[1] - __half2float(p1);
                nh[r] = (uint32_t)(*(unsigned short*)&p0) |
                        ((uint32_t)(*(unsigned short*)&p1) << 16);
                nl[r] = pack_h2(r0, r1);
            }
            Ah[q][0][wid][mt][lane] = make_uint4(nh[0], nh[1], nh[2], nh[3]);
            Ah[q][1][wid][mt][lane] = make_uint4(nl[0], nl[1], nl[2], nl[3]);
        }

        if (t < TSTEPS - 1) st_x(q, pv0, pv1);
        __syncthreads();   // buf q complete + all buf p reads done -> next step
    }

    // ---- dense + softmax ----
    if (tid < TILE_B) {
        const int row = tid;
        float lg[NCLS];
#pragma unroll
        for (int c = 0; c < NCLS; c++) lg[c] = db[c];
        for (int j = 0; j < HID; j++) {
            float hv = hs[row][j];
#pragma unroll
            for (int c = 0; c < NCLS; c++) lg[c] = fmaf(hv, dw[j * NCLS + c], lg[c]);
        }
        float m = lg[0];
#pragma unroll
        for (int c = 1; c < NCLS; c++) m = fmaxf(m, lg[c]);
        float s = 0.0f;
#pragma unroll
        for (int c = 0; c < NCLS; c++) { lg[c] = expf(lg[c] - m); s += lg[c]; }
        float inv = __fdividef(1.0f, s);
#pragma unroll
        for (int c = 0; c < NCLS; c++)
            out[(size_t)(b0 + row) * NCLS + c] = lg[c] * inv;
    }
}

extern "C" void kernel_launch(void* const* d_in, const int* in_sizes, int n_in,
                              void* d_out, int out_size) {
    const float* x    = (const float*)d_in[0];
    const float* Wk   = (const float*)d_in[1];
    const float* Rk   = (const float*)d_in[2];
    const float* bias = (const float*)d_in[3];
    const float* dw   = (const float*)d_in[4];
    const float* db   = (const float*)d_in[5];
    float* out = (float*)d_out;

    prep_B<<<(NBFR + 255) / 256, 256>>>(Rk, Wk);
    gru_hmma_kernel<<<NBLK, NTH>>>(x, bias, dw, db, out);
}

// round 13
// speedup vs baseline: 2.6177x; 1.2811x over previous
#include <cuda_runtime.h>
#include <cuda_fp16.h>
#include <cstdint>
#include <math.h>

#define BATCH   16384
#define TSTEPS  28
#define FEAT    28
#define HID     128
#define G3      384
#define NCLS    10

#define TILE_B  32
#define NTH     256
#define NKT     10          // K chunks of 16: kt 0..7 = h (k=j), kt 8,9 = x
#define NBLK    (BATCH / TILE_B)
#define NBFR    (8 * NKT * 4 * 2 * 32)

// B operand (fp16), fragment-linear:
// index [w(8)][kt(10)][g(4)][nt(2)][lane(32)] : uint2 {b0, b1}
__device__ __align__(16) uint2 gB_hi[NBFR];

__device__ __forceinline__ float2 unpack_h2(uint32_t u) {
    __half2 p = *reinterpret_cast<__half2*>(&u);
    return __half22float2(p);
}

__device__ __forceinline__ void mma16816(float* c, const uint4& a,
                                         uint32_t b0, uint32_t b1) {
    asm volatile(
        "mma.sync.aligned.m16n8k16.row.col.f32.f16.f16.f32 "
        "{%0,%1,%2,%3}, {%4,%5,%6,%7}, {%8,%9}, {%0,%1,%2,%3};"
        : "+f"(c[0]), "+f"(c[1]), "+f"(c[2]), "+f"(c[3])
        : "r"(a.x), "r"(a.y), "r"(a.z), "r"(a.w), "r"(b0), "r"(b1));
}

// HW tanh (sm_75+): 1 MUFU op, rel err ~2^-11
__device__ __forceinline__ float tanh_hw(float v) {
    float r;
    asm("tanh.approx.f32 %0, %1;" : "=f"(r) : "f"(v));
    return r;
}
// sigmoid via tanh identity: 1 MUFU + 2 FMA
__device__ __forceinline__ float sig_(float v) {
    return fmaf(0.5f, tanh_hw(0.5f * v), 0.5f);
}

// ---------------------------------------------------------------------------
// Prep: weights -> fragment-linear fp16 (round-to-nearest).
// g: 0=z(col j), 1=r(col 128+j), 2=rh(col 256+j, R rows), 3=xh(col 256+j, W rows)
// ---------------------------------------------------------------------------
__global__ void prep_B(const float* __restrict__ Rk, const float* __restrict__ Wk) {
    int idx = blockIdx.x * blockDim.x + threadIdx.x;
    if (idx >= NBFR) return;
    int lane = idx & 31;
    int nt   = (idx >> 5) & 1;
    int g    = (idx >> 6) & 3;
    int kt   = (idx >> 8) % NKT;
    int w    = (idx >> 8) / NKT;
    int gid  = lane >> 2, tg = lane & 3;

    int jloc = 16 * w + 8 * nt + gid;
    int wcol = (g == 0) ? jloc : (g == 1 ? 128 + jloc : 256 + jloc);
    int k0   = kt * 16 + tg * 2;

    float v[4];
#pragma unroll
    for (int i = 0; i < 4; i++) {
        int k = k0 + (i >> 1) * 8 + (i & 1);
        float val = 0.0f;
        if (k < HID) { if (g != 3) val = Rk[k * G3 + wcol]; }
        else { int f = k - HID; if (f < FEAT && g != 2) val = Wk[f * G3 + wcol]; }
        v[i] = val;
    }
    __half h[4];
#pragma unroll
    for (int i = 0; i < 4; i++) h[i] = __float2half_rn(v[i]);
    uint2 fh;
    fh.x = (uint32_t)(*(unsigned short*)&h[0]) | ((uint32_t)(*(unsigned short*)&h[1]) << 16);
    fh.y = (uint32_t)(*(unsigned short*)&h[2]) | ((uint32_t)(*(unsigned short*)&h[3]) << 16);
    gB_hi[idx] = fh;
}

// ---------------------------------------------------------------------------
// Main fused GRU: persistent per-block scan, HMMA core.
// Round 13: single fp16 A (no lo split) -> -25% MMA, -50% A smem traffic;
//           old-h preloaded before mainloop.
// ---------------------------------------------------------------------------
__global__ void __launch_bounds__(NTH, 2)
gru_hmma_kernel(const float* __restrict__ x,
                const float* __restrict__ bias,
                const float* __restrict__ dw,
                const float* __restrict__ db,
                float* __restrict__ out)
{
    __shared__ uint4 Ah[2][NKT][2][32];      // [buf][kt][mt][lane], fp16 frags
    __shared__ float hs[TILE_B][HID + 1];

    const int tid  = threadIdx.x;
    const int wid  = tid >> 5;
    const int lane = tid & 31;
    const int gid  = lane >> 2;
    const int tg   = lane & 3;
    const int b0   = blockIdx.x * TILE_B;
    const float* xg = x + (size_t)b0 * (TSTEPS * FEAT);

    // zero buffer 0 (h region must start as 0; buf 1 fully written in step 0)
    for (int i = tid; i < NKT * 2 * 32; i += NTH)
        ((uint4*)Ah[0])[i] = make_uint4(0, 0, 0, 0);

    // bias -> accumulator-init registers: bp[u][e], u = g*2+nt
    float bp[8][2];
#pragma unroll
    for (int g = 0; g < 4; g++)
#pragma unroll
        for (int nt = 0; nt < 2; nt++) {
            int jl = 16 * wid + 8 * nt + 2 * tg;
#pragma unroll
            for (int e = 0; e < 2; e++) {
                int j = jl + e;
                float v;
                if      (g == 0) v = bias[j]       + bias[G3 + j];
                else if (g == 1) v = bias[128 + j] + bias[G3 + 128 + j];
                else if (g == 2) v = bias[G3 + 256 + j];
                else             v = bias[256 + j];
                bp[g * 2 + nt][e] = v;
            }
        }

    // per-thread x staging geometry (2 slots/thread)
    int xrow[2], xkl[2], xmt[2], xkt8[2], xr[2], xln[2];
#pragma unroll
    for (int i = 0; i < 2; i++) {
        int s   = tid * 2 + i;
        xr[i]   = s & 3;
        xln[i]  = (s >> 2) & 31;
        xmt[i]  = (s >> 7) & 1;
        xkt8[i] = s >> 8;
        int gd = xln[i] >> 2, tgg = xln[i] & 3;
        xrow[i] = xmt[i] * 16 + gd + 8 * (xr[i] & 1);
        xkl[i]  = xkt8[i] * 16 + tgg * 2 + 8 * (xr[i] >> 1);
    }

    auto ld_x = [&](int t, float* v0, float* v1) {
#pragma unroll
        for (int i = 0; i < 2; i++) {
            v0[i] = 0.0f; v1[i] = 0.0f;
            if (xkl[i] < FEAT) {
                const float* p = xg + (size_t)xrow[i] * (TSTEPS * FEAT) + t * FEAT + xkl[i];
                v0[i] = __ldg(p);
                if (xkl[i] + 1 < FEAT) v1[i] = __ldg(p + 1);
            }
        }
    };
    auto st_x = [&](int buf, const float* v0, const float* v1) {
#pragma unroll
        for (int i = 0; i < 2; i++) {
            __half h0 = __float2half_rn(v0[i]), h1 = __float2half_rn(v1[i]);
            ((uint32_t*)&Ah[buf][8 + xkt8[i]][xmt[i]][xln[i]])[xr[i]] =
                (uint32_t)(*(unsigned short*)&h0) | ((uint32_t)(*(unsigned short*)&h1) << 16);
        }
    };

    {   // stage x(0) into buffer 0
        float v0[2], v1[2];
        ld_x(0, v0, v1);
        st_x(0, v0, v1);
    }
    __syncthreads();

    float acc[2][8][4];

#pragma unroll 1
    for (int t = 0; t < TSTEPS; t++) {
        const int p = t & 1;         // read buffer
        const int q = p ^ 1;         // write buffer (next step's read)

        // prefetch x(t+1) into registers (latency hidden behind mainloop MMAs)
        float pv0[2], pv1[2];
        if (t < TSTEPS - 1) ld_x(t + 1, pv0, pv1);

        // preload this warp's old-h fragments (kt = wid) for the epilogue
        const uint4 oldh0 = Ah[p][wid][0][lane];
        const uint4 oldh1 = Ah[p][wid][1][lane];

#pragma unroll
        for (int mt = 0; mt < 2; mt++)
#pragma unroll
            for (int u = 0; u < 8; u++) {
                acc[mt][u][0] = bp[u][0]; acc[mt][u][1] = bp[u][1];
                acc[mt][u][2] = bp[u][0]; acc[mt][u][3] = bp[u][1];
            }

        // ---- HMMA mainloop (reads buf p): single fp16 pass ----
#pragma unroll
        for (int kt = 0; kt < NKT; kt++) {
            const uint4 A0 = Ah[p][kt][0][lane];
            const uint4 A1 = Ah[p][kt][1][lane];
            // active gate groups: kt<8 -> {z, r, rh}; kt>=8 -> {z, r, xh}
            const int g2 = (kt < 8) ? 2 : 3;
            const int gs[3] = {0, 1, g2};

            uint2 Bh[3][2];
#pragma unroll
            for (int gi = 0; gi < 3; gi++) {
                const int base = (((wid * NKT + kt) * 4 + gs[gi]) * 2) * 32 + lane;
                Bh[gi][0] = __ldg(&gB_hi[base]);
                Bh[gi][1] = __ldg(&gB_hi[base + 32]);
            }

#pragma unroll
            for (int gi = 0; gi < 3; gi++)
#pragma unroll
                for (int nt = 0; nt < 2; nt++) {
                    const int u = gs[gi] * 2 + nt;
                    mma16816(acc[0][u], A0, Bh[gi][nt].x, Bh[gi][nt].y);
                    mma16816(acc[1][u], A1, Bh[gi][nt].x, Bh[gi][nt].y);
                }
        }
        // NO barrier here: epilogue writes go to buf q, mainloop readers use buf p.

        // ---- epilogue: gates in-register; write new h frags to buf q ----
#pragma unroll
        for (int mt = 0; mt < 2; mt++) {
            const uint4 Hh = (mt == 0) ? oldh0 : oldh1;
            const uint32_t hh_[4] = {Hh.x, Hh.y, Hh.z, Hh.w};
            uint32_t nh[4];
#pragma unroll
            for (int r = 0; r < 4; r++) {
                const int nt = r >> 1;
                const int ci = (r & 1) * 2;
                float2 oh = unpack_h2(hh_[r]);
                float hold[2] = {oh.x, oh.y};
                float hnew[2];
#pragma unroll
                for (int e = 0; e < 2; e++) {
                    float z  = sig_(acc[mt][0 + nt][ci + e]);
                    float rr = sig_(acc[mt][2 + nt][ci + e]);
                    float hc = tanh_hw(acc[mt][6 + nt][ci + e] + rr * acc[mt][4 + nt][ci + e]);
                    hnew[e] = hc + z * (hold[e] - hc);
                    if (t == TSTEPS - 1) {
                        int row = mt * 16 + gid + 8 * (r & 1);
                        int j   = 16 * wid + 8 * nt + 2 * tg + e;
                        hs[row][j] = hnew[e];
                    }
                }
                __half p0 = __float2half_rn(hnew[0]), p1 = __float2half_rn(hnew[1]);
                nh[r] = (uint32_t)(*(unsigned short*)&p0) |
                        ((uint32_t)(*(unsigned short*)&p1) << 16);
            }
            Ah[q][wid][mt][lane] = make_uint4(nh[0], nh[1], nh[2], nh[3]);
        }

        if (t < TSTEPS - 1) st_x(q, pv0, pv1);
        __syncthreads();   // buf q complete + all buf p reads done -> next step
    }

    // ---- dense + softmax ----
    if (tid < TILE_B) {
        const int row = tid;
        float lg[NCLS];
#pragma unroll
        for (int c = 0; c < NCLS; c++) lg[c] = db[c];
        for (int j = 0; j < HID; j++) {
            float hv = hs[row][j];
#pragma unroll
            for (int c = 0; c < NCLS; c++) lg[c] = fmaf(hv, dw[j * NCLS + c], lg[c]);
        }
        float m = lg[0];
#pragma unroll
        for (int c = 1; c < NCLS; c++) m = fmaxf(m, lg[c]);
        float s = 0.0f;
#pragma unroll
        for (int c = 0; c < NCLS; c++) { lg[c] = expf(lg[c] - m); s += lg[c]; }
        float inv = __fdividef(1.0f, s);
#pragma unroll
        for (int c = 0; c < NCLS; c++)
            out[(size_t)(b0 + row) * NCLS + c] = lg[c] * inv;
    }
}

extern "C" void kernel_launch(void* const* d_in, const int* in_sizes, int n_in,
                              void* d_out, int out_size) {
    const float* x    = (const float*)d_in[0];
    const float* Wk   = (const float*)d_in[1];
    const float* Rk   = (const float*)d_in[2];
    const float* bias = (const float*)d_in[3];
    const float* dw   = (const float*)d_in[4];
    const float* db   = (const float*)d_in[5];
    float* out = (float*)d_out;

    prep_B<<<(NBFR + 255) / 256, 256>>>(Rk, Wk);
    gru_hmma_kernel<<<NBLK, NTH>>>(x, bias, dw, db, out);
}

// round 14
// speedup vs baseline: 2.6335x; 1.0061x over previous
#include <cuda_runtime.h>
#include <cuda_fp16.h>
#include <cstdint>
#include <math.h>

#define BATCH   16384
#define TSTEPS  28
#define FEAT    28
#define HID     128
#define G3      384
#define NCLS    10

#define TILE_B  32
#define NTH     256
#define NKT     10          // K chunks of 16: kt 0..7 = h (k=j), kt 8,9 = x
#define NBLK    (BATCH / TILE_B)
#define NBFR4   (8 * NKT * 4 * 32)   // paired fragments

// B operand (fp16), fragment-linear, nt-PAIRED:
// index [w(8)][kt(10)][g(4)][lane(32)] : uint4 {nt0.b0, nt0.b1, nt1.b0, nt1.b1}
__device__ __align__(16) uint4 gB4[NBFR4];

__device__ __forceinline__ float2 unpack_h2(uint32_t u) {
    __half2 p = *reinterpret_cast<__half2*>(&u);
    return __half22float2(p);
}

__device__ __forceinline__ void mma16816(float* c, const uint4& a,
                                         uint32_t b0, uint32_t b1) {
    asm volatile(
        "mma.sync.aligned.m16n8k16.row.col.f32.f16.f16.f32 "
        "{%0,%1,%2,%3}, {%4,%5,%6,%7}, {%8,%9}, {%0,%1,%2,%3};"
        : "+f"(c[0]), "+f"(c[1]), "+f"(c[2]), "+f"(c[3])
        : "r"(a.x), "r"(a.y), "r"(a.z), "r"(a.w), "r"(b0), "r"(b1));
}

// HW tanh (sm_75+): 1 MUFU op, rel err ~2^-11
__device__ __forceinline__ float tanh_hw(float v) {
    float r;
    asm("tanh.approx.f32 %0, %1;" : "=f"(r) : "f"(v));
    return r;
}
// sigmoid via tanh identity: 1 MUFU + 2 FMA
__device__ __forceinline__ float sig_(float v) {
    return fmaf(0.5f, tanh_hw(0.5f * v), 0.5f);
}

// ---------------------------------------------------------------------------
// Prep: weights -> nt-paired fragment-linear fp16.
// g: 0=z(col j), 1=r(col 128+j), 2=rh(col 256+j, R rows), 3=xh(col 256+j, W rows)
// ---------------------------------------------------------------------------
__global__ void prep_B(const float* __restrict__ Rk, const float* __restrict__ Wk) {
    int idx = blockIdx.x * blockDim.x + threadIdx.x;
    if (idx >= NBFR4) return;
    int lane = idx & 31;
    int g    = (idx >> 5) & 3;
    int kt   = (idx >> 7) % NKT;
    int w    = (idx >> 7) / NKT;
    int gid  = lane >> 2, tg = lane & 3;
    int k0   = kt * 16 + tg * 2;

    uint32_t words[2][2];
#pragma unroll
    for (int nt = 0; nt < 2; nt++) {
        int jloc = 16 * w + 8 * nt + gid;
        int wcol = (g == 0) ? jloc : (g == 1 ? 128 + jloc : 256 + jloc);
        __half h[4];
#pragma unroll
        for (int i = 0; i < 4; i++) {
            int k = k0 + (i >> 1) * 8 + (i & 1);
            float val = 0.0f;
            if (k < HID) { if (g != 3) val = Rk[k * G3 + wcol]; }
            else { int f = k - HID; if (f < FEAT && g != 2) val = Wk[f * G3 + wcol]; }
            h[i] = __float2half_rn(val);
        }
        words[nt][0] = (uint32_t)(*(unsigned short*)&h[0]) |
                       ((uint32_t)(*(unsigned short*)&h[1]) << 16);
        words[nt][1] = (uint32_t)(*(unsigned short*)&h[2]) |
                       ((uint32_t)(*(unsigned short*)&h[3]) << 16);
    }
    gB4[idx] = make_uint4(words[0][0], words[0][1], words[1][0], words[1][1]);
}

// ---------------------------------------------------------------------------
// Main fused GRU: persistent per-block scan, HMMA core.
// Round 14: nt-paired B fragments -> LDG.128, half the load instructions.
// ---------------------------------------------------------------------------
__global__ void __launch_bounds__(NTH, 2)
gru_hmma_kernel(const float* __restrict__ x,
                const float* __restrict__ bias,
                const float* __restrict__ dw,
                const float* __restrict__ db,
                float* __restrict__ out)
{
    __shared__ uint4 Ah[2][NKT][2][32];      // [buf][kt][mt][lane], fp16 frags
    __shared__ float hs[TILE_B][HID + 1];

    const int tid  = threadIdx.x;
    const int wid  = tid >> 5;
    const int lane = tid & 31;
    const int gid  = lane >> 2;
    const int tg   = lane & 3;
    const int b0   = blockIdx.x * TILE_B;
    const float* xg = x + (size_t)b0 * (TSTEPS * FEAT);

    // zero buffer 0 (h region must start as 0; buf 1 fully written in step 0)
    for (int i = tid; i < NKT * 2 * 32; i += NTH)
        ((uint4*)Ah[0])[i] = make_uint4(0, 0, 0, 0);

    // bias -> accumulator-init registers: bp[u][e], u = g*2+nt
    float bp[8][2];
#pragma unroll
    for (int g = 0; g < 4; g++)
#pragma unroll
        for (int nt = 0; nt < 2; nt++) {
            int jl = 16 * wid + 8 * nt + 2 * tg;
#pragma unroll
            for (int e = 0; e < 2; e++) {
                int j = jl + e;
                float v;
                if      (g == 0) v = bias[j]       + bias[G3 + j];
                else if (g == 1) v = bias[128 + j] + bias[G3 + 128 + j];
                else if (g == 2) v = bias[G3 + 256 + j];
                else             v = bias[256 + j];
                bp[g * 2 + nt][e] = v;
            }
        }

    // per-thread x staging geometry (2 slots/thread)
    int xrow[2], xkl[2], xmt[2], xkt8[2], xr[2], xln[2];
#pragma unroll
    for (int i = 0; i < 2; i++) {
        int s   = tid * 2 + i;
        xr[i]   = s & 3;
        xln[i]  = (s >> 2) & 31;
        xmt[i]  = (s >> 7) & 1;
        xkt8[i] = s >> 8;
        int gd = xln[i] >> 2, tgg = xln[i] & 3;
        xrow[i] = xmt[i] * 16 + gd + 8 * (xr[i] & 1);
        xkl[i]  = xkt8[i] * 16 + tgg * 2 + 8 * (xr[i] >> 1);
    }

    auto ld_x = [&](int t, float* v0, float* v1) {
#pragma unroll
        for (int i = 0; i < 2; i++) {
            v0[i] = 0.0f; v1[i] = 0.0f;
            if (xkl[i] < FEAT) {
                const float* p = xg + (size_t)xrow[i] * (TSTEPS * FEAT) + t * FEAT + xkl[i];
                v0[i] = __ldg(p);
                if (xkl[i] + 1 < FEAT) v1[i] = __ldg(p + 1);
            }
        }
    };
    auto st_x = [&](int buf, const float* v0, const float* v1) {
#pragma unroll
        for (int i = 0; i < 2; i++) {
            __half h0 = __float2half_rn(v0[i]), h1 = __float2half_rn(v1[i]);
            ((uint32_t*)&Ah[buf][8 + xkt8[i]][xmt[i]][xln[i]])[xr[i]] =
                (uint32_t)(*(unsigned short*)&h0) | ((uint32_t)(*(unsigned short*)&h1) << 16);
        }
    };

    {   // stage x(0) into buffer 0
        float v0[2], v1[2];
        ld_x(0, v0, v1);
        st_x(0, v0, v1);
    }
    __syncthreads();

    float acc[2][8][4];

#pragma unroll 1
    for (int t = 0; t < TSTEPS; t++) {
        const int p = t & 1;         // read buffer
        const int q = p ^ 1;         // write buffer (next step's read)

        // prefetch x(t+1) into registers (latency hidden behind mainloop MMAs)
        float pv0[2], pv1[2];
        if (t < TSTEPS - 1) ld_x(t + 1, pv0, pv1);

        // preload this warp's old-h fragments (kt = wid) for the epilogue
        const uint4 oldh0 = Ah[p][wid][0][lane];
        const uint4 oldh1 = Ah[p][wid][1][lane];

#pragma unroll
        for (int mt = 0; mt < 2; mt++)
#pragma unroll
            for (int u = 0; u < 8; u++) {
                acc[mt][u][0] = bp[u][0]; acc[mt][u][1] = bp[u][1];
                acc[mt][u][2] = bp[u][0]; acc[mt][u][3] = bp[u][1];
            }

        // ---- HMMA mainloop (reads buf p): single fp16 pass, LDG.128 B ----
#pragma unroll
        for (int kt = 0; kt < NKT; kt++) {
            const uint4 A0 = Ah[p][kt][0][lane];
            const uint4 A1 = Ah[p][kt][1][lane];
            // active gate groups: kt<8 -> {z, r, rh}; kt>=8 -> {z, r, xh}
            const int g2 = (kt < 8) ? 2 : 3;
            const int gs[3] = {0, 1, g2};

            uint4 B[3];
#pragma unroll
            for (int gi = 0; gi < 3; gi++)
                B[gi] = __ldg(&gB4[((wid * NKT + kt) * 4 + gs[gi]) * 32 + lane]);

#pragma unroll
            for (int gi = 0; gi < 3; gi++) {
                const int u0 = gs[gi] * 2, u1 = u0 + 1;
                mma16816(acc[0][u0], A0, B[gi].x, B[gi].y);
                mma16816(acc[1][u0], A1, B[gi].x, B[gi].y);
                mma16816(acc[0][u1], A0, B[gi].z, B[gi].w);
                mma16816(acc[1][u1], A1, B[gi].z, B[gi].w);
            }
        }
        // NO barrier here: epilogue writes go to buf q, mainloop readers use buf p.

        // ---- epilogue: gates in-register; write new h frags to buf q ----
#pragma unroll
        for (int mt = 0; mt < 2; mt++) {
            const uint4 Hh = (mt == 0) ? oldh0 : oldh1;
            const uint32_t hh_[4] = {Hh.x, Hh.y, Hh.z, Hh.w};
            uint32_t nh[4];
#pragma unroll
            for (int r = 0; r < 4; r++) {
                const int nt = r >> 1;
                const int ci = (r & 1) * 2;
                float2 oh = unpack_h2(hh_[r]);
                float hold[2] = {oh.x, oh.y};
                float hnew[2];
#pragma unroll
                for (int e = 0; e < 2; e++) {
                    float z  = sig_(acc[mt][0 + nt][ci + e]);
                    float rr = sig_(acc[mt][2 + nt][ci + e]);
                    float hc = tanh_hw(acc[mt][6 + nt][ci + e] + rr * acc[mt][4 + nt][ci + e]);
                    hnew[e] = hc + z * (hold[e] - hc);
                    if (t == TSTEPS - 1) {
                        int row = mt * 16 + gid + 8 * (r & 1);
                        int j   = 16 * wid + 8 * nt + 2 * tg + e;
                        hs[row][j] = hnew[e];
                    }
                }
                __half p0 = __float2half_rn(hnew[0]), p1 = __float2half_rn(hnew[1]);
                nh[r] = (uint32_t)(*(unsigned short*)&p0) |
                        ((uint32_t)(*(unsigned short*)&p1) << 16);
            }
            Ah[q][wid][mt][lane] = make_uint4(nh[0], nh[1], nh[2], nh[3]);
        }

        if (t < TSTEPS - 1) st_x(q, pv0, pv1);
        __syncthreads();   // buf q complete + all buf p reads done -> next step
    }

    // ---- dense + softmax ----
    if (tid < TILE_B) {
        const int row = tid;
        float lg[NCLS];
#pragma unroll
        for (int c = 0; c < NCLS; c++) lg[c] = db[c];
        for (int j = 0; j < HID; j++) {
            float hv = hs[row][j];
#pragma unroll
            for (int c = 0; c < NCLS; c++) lg[c] = fmaf(hv, dw[j * NCLS + c], lg[c]);
        }
        float m = lg[0];
#pragma unroll
        for (int c = 1; c < NCLS; c++) m = fmaxf(m, lg[c]);
        float s = 0.0f;
#pragma unroll
        for (int c = 0; c < NCLS; c++) { lg[c] = expf(lg[c] - m); s += lg[c]; }
        float inv = __fdividef(1.0f, s);
#pragma unroll
        for (int c = 0; c < NCLS; c++)
            out[(size_t)(b0 + row) * NCLS + c] = lg[c] * inv;
    }
}

extern "C" void kernel_launch(void* const* d_in, const int* in_sizes, int n_in,
                              void* d_out, int out_size) {
    const float* x    = (const float*)d_in[0];
    const float* Wk   = (const float*)d_in[1];
    const float* Rk   = (const float*)d_in[2];
    const float* bias = (const float*)d_in[3];
    const float* dw   = (const float*)d_in[4];
    const float* db   = (const float*)d_in[5];
    float* out = (float*)d_out;

    prep_B<<<(NBFR4 + 255) / 256, 256>>>(Rk, Wk);
    gru_hmma_kernel<<<NBLK, NTH>>>(x, bias, dw, db, out);
}

// round 15
// speedup vs baseline: 2.6926x; 1.0224x over previous
#include <cuda_runtime.h>
#include <cuda_fp16.h>
#include <cstdint>
#include <math.h>

#define BATCH   16384
#define TSTEPS  28
#define FEAT    28
#define HID     128
#define G3      384
#define NCLS    10

#define TILE_B  32
#define NTH     256
#define NKT     10          // K chunks of 16: kt 0..7 = h (k=j), kt 8,9 = x
#define NBLK    (BATCH / TILE_B)
#define NBFR4   (8 * NKT * 4 * 32)   // paired fragments

// B operand (fp16), fragment-linear, nt-PAIRED:
// index [w(8)][kt(10)][g(4)][lane(32)] : uint4 {nt0.b0, nt0.b1, nt1.b0, nt1.b1}
__device__ __align__(16) uint4 gB4[NBFR4];

__device__ __forceinline__ void mma16816(float* c, const uint4& a,
                                         uint32_t b0, uint32_t b1) {
    asm volatile(
        "mma.sync.aligned.m16n8k16.row.col.f32.f16.f16.f32 "
        "{%0,%1,%2,%3}, {%4,%5,%6,%7}, {%8,%9}, {%0,%1,%2,%3};"
        : "+f"(c[0]), "+f"(c[1]), "+f"(c[2]), "+f"(c[3])
        : "r"(a.x), "r"(a.y), "r"(a.z), "r"(a.w), "r"(b0), "r"(b1));
}

// HW tanh, packed fp16x2: 1 MUFU op for TWO elements
__device__ __forceinline__ __half2 tanh2_hw(__half2 v) {
    __half2 r;
    asm("tanh.approx.f16x2 %0, %1;"
        : "=r"(*(uint32_t*)&r) : "r"(*(uint32_t*)&v));
    return r;
}
// fp32 HW tanh (dense head / scalar paths)
__device__ __forceinline__ float tanh_hw(float v) {
    float r;
    asm("tanh.approx.f32 %0, %1;" : "=f"(r) : "f"(v));
    return r;
}

// ---------------------------------------------------------------------------
// Prep: weights -> nt-paired fragment-linear fp16.
// g: 0=z(col j), 1=r(col 128+j), 2=rh(col 256+j, R rows), 3=xh(col 256+j, W rows)
// ---------------------------------------------------------------------------
__global__ void prep_B(const float* __restrict__ Rk, const float* __restrict__ Wk) {
    int idx = blockIdx.x * blockDim.x + threadIdx.x;
    if (idx >= NBFR4) return;
    int lane = idx & 31;
    int g    = (idx >> 5) & 3;
    int kt   = (idx >> 7) % NKT;
    int w    = (idx >> 7) / NKT;
    int gid  = lane >> 2, tg = lane & 3;
    int k0   = kt * 16 + tg * 2;

    uint32_t words[2][2];
#pragma unroll
    for (int nt = 0; nt < 2; nt++) {
        int jloc = 16 * w + 8 * nt + gid;
        int wcol = (g == 0) ? jloc : (g == 1 ? 128 + jloc : 256 + jloc);
        __half h[4];
#pragma unroll
        for (int i = 0; i < 4; i++) {
            int k = k0 + (i >> 1) * 8 + (i & 1);
            float val = 0.0f;
            if (k < HID) { if (g != 3) val = Rk[k * G3 + wcol]; }
            else { int f = k - HID; if (f < FEAT && g != 2) val = Wk[f * G3 + wcol]; }
            h[i] = __float2half_rn(val);
        }
        words[nt][0] = (uint32_t)(*(unsigned short*)&h[0]) |
                       ((uint32_t)(*(unsigned short*)&h[1]) << 16);
        words[nt][1] = (uint32_t)(*(unsigned short*)&h[2]) |
                       ((uint32_t)(*(unsigned short*)&h[3]) << 16);
    }
    gB4[idx] = make_uint4(words[0][0], words[0][1], words[1][0], words[1][1]);
}

// ---------------------------------------------------------------------------
// Main fused GRU: persistent per-block scan, HMMA core.
// Round 15: fp16x2 vectorized epilogue (tanh.approx.f16x2, HFMA2 update,
//           results land pre-packed in fragment format).
// ---------------------------------------------------------------------------
__global__ void __launch_bounds__(NTH, 2)
gru_hmma_kernel(const float* __restrict__ x,
                const float* __restrict__ bias,
                const float* __restrict__ dw,
                const float* __restrict__ db,
                float* __restrict__ out)
{
    __shared__ uint4 Ah[2][NKT][2][32];      // [buf][kt][mt][lane], fp16 frags
    __shared__ float hs[TILE_B][HID + 1];

    const int tid  = threadIdx.x;
    const int wid  = tid >> 5;
    const int lane = tid & 31;
    const int gid  = lane >> 2;
    const int tg   = lane & 3;
    const int b0   = blockIdx.x * TILE_B;
    const float* xg = x + (size_t)b0 * (TSTEPS * FEAT);

    // zero buffer 0 (h region must start as 0; buf 1 fully written in step 0)
    for (int i = tid; i < NKT * 2 * 32; i += NTH)
        ((uint4*)Ah[0])[i] = make_uint4(0, 0, 0, 0);

    // bias -> accumulator-init registers: bp[u][e], u = g*2+nt
    float bp[8][2];
#pragma unroll
    for (int g = 0; g < 4; g++)
#pragma unroll
        for (int nt = 0; nt < 2; nt++) {
            int jl = 16 * wid + 8 * nt + 2 * tg;
#pragma unroll
            for (int e = 0; e < 2; e++) {
                int j = jl + e;
                float v;
                if      (g == 0) v = bias[j]       + bias[G3 + j];
                else if (g == 1) v = bias[128 + j] + bias[G3 + 128 + j];
                else if (g == 2) v = bias[G3 + 256 + j];
                else             v = bias[256 + j];
                bp[g * 2 + nt][e] = v;
            }
        }

    // per-thread x staging geometry (2 slots/thread)
    int xrow[2], xkl[2], xmt[2], xkt8[2], xr[2], xln[2];
#pragma unroll
    for (int i = 0; i < 2; i++) {
        int s   = tid * 2 + i;
        xr[i]   = s & 3;
        xln[i]  = (s >> 2) & 31;
        xmt[i]  = (s >> 7) & 1;
        xkt8[i] = s >> 8;
        int gd = xln[i] >> 2, tgg = xln[i] & 3;
        xrow[i] = xmt[i] * 16 + gd + 8 * (xr[i] & 1);
        xkl[i]  = xkt8[i] * 16 + tgg * 2 + 8 * (xr[i] >> 1);
    }

    auto ld_x = [&](int t, float* v0, float* v1) {
#pragma unroll
        for (int i = 0; i < 2; i++) {
            v0[i] = 0.0f; v1[i] = 0.0f;
            if (xkl[i] < FEAT) {
                const float* p = xg + (size_t)xrow[i] * (TSTEPS * FEAT) + t * FEAT + xkl[i];
                v0[i] = __ldg(p);
                if (xkl[i] + 1 < FEAT) v1[i] = __ldg(p + 1);
            }
        }
    };
    auto st_x = [&](int buf, const float* v0, const float* v1) {
#pragma unroll
        for (int i = 0; i < 2; i++) {
            __half2 hx = __floats2half2_rn(v0[i], v1[i]);  // low = v0 (k), high = v1 (k+1)
            ((uint32_t*)&Ah[buf][8 + xkt8[i]][xmt[i]][xln[i]])[xr[i]] = *(uint32_t*)&hx;
        }
    };

    {   // stage x(0) into buffer 0
        float v0[2], v1[2];
        ld_x(0, v0, v1);
        st_x(0, v0, v1);
    }
    __syncthreads();

    float acc[2][8][4];
    const __half2 H05 = __float2half2_rn(0.5f);

#pragma unroll 1
    for (int t = 0; t < TSTEPS; t++) {
        const int p = t & 1;         // read buffer
        const int q = p ^ 1;         // write buffer (next step's read)

        // prefetch x(t+1) into registers (latency hidden behind mainloop MMAs)
        float pv0[2], pv1[2];
        if (t < TSTEPS - 1) ld_x(t + 1, pv0, pv1);

        // preload this warp's old-h fragments (kt = wid) for the epilogue
        const uint4 oldh0 = Ah[p][wid][0][lane];
        const uint4 oldh1 = Ah[p][wid][1][lane];

#pragma unroll
        for (int mt = 0; mt < 2; mt++)
#pragma unroll
            for (int u = 0; u < 8; u++) {
                acc[mt][u][0] = bp[u][0]; acc[mt][u][1] = bp[u][1];
                acc[mt][u][2] = bp[u][0]; acc[mt][u][3] = bp[u][1];
            }

        // ---- HMMA mainloop (reads buf p): single fp16 pass, LDG.128 B ----
#pragma unroll
        for (int kt = 0; kt < NKT; kt++) {
            const uint4 A0 = Ah[p][kt][0][lane];
            const uint4 A1 = Ah[p][kt][1][lane];
            // active gate groups: kt<8 -> {z, r, rh}; kt>=8 -> {z, r, xh}
            const int g2 = (kt < 8) ? 2 : 3;
            const int gs[3] = {0, 1, g2};

            uint4 B[3];
#pragma unroll
            for (int gi = 0; gi < 3; gi++)
                B[gi] = __ldg(&gB4[((wid * NKT + kt) * 4 + gs[gi]) * 32 + lane]);

#pragma unroll
            for (int gi = 0; gi < 3; gi++) {
                const int u0 = gs[gi] * 2, u1 = u0 + 1;
                mma16816(acc[0][u0], A0, B[gi].x, B[gi].y);
                mma16816(acc[1][u0], A1, B[gi].x, B[gi].y);
                mma16816(acc[0][u1], A0, B[gi].z, B[gi].w);
                mma16816(acc[1][u1], A1, B[gi].z, B[gi].w);
            }
        }
        // NO barrier here: epilogue writes go to buf q, mainloop readers use buf p.

        // ---- epilogue (fp16x2): gates packed 2-wide; output pre-packed ----
#pragma unroll
        for (int mt = 0; mt < 2; mt++) {
            const uint4 Hh = (mt == 0) ? oldh0 : oldh1;
            const uint32_t hh_[4] = {Hh.x, Hh.y, Hh.z, Hh.w};
            uint32_t nh[4];
#pragma unroll
            for (int r = 0; r < 4; r++) {
                const int nt = r >> 1;
                const int ci = (r & 1) * 2;
                // pack accumulator pairs (e=0 low, e=1 high — matches frag layout)
                __half2 az2 = __floats2half2_rn(acc[mt][0 + nt][ci], acc[mt][0 + nt][ci + 1]);
                __half2 ar2 = __floats2half2_rn(acc[mt][2 + nt][ci], acc[mt][2 + nt][ci + 1]);
                __half2 ah2 = __floats2half2_rn(acc[mt][4 + nt][ci], acc[mt][4 + nt][ci + 1]);
                __half2 ax2 = __floats2half2_rn(acc[mt][6 + nt][ci], acc[mt][6 + nt][ci + 1]);
                // z = 0.5 + 0.5*tanh(0.5*az); r likewise (1 MUFU per 2 elems)
                __half2 z2 = __hfma2(tanh2_hw(__hmul2(az2, H05)), H05, H05);
                __half2 r2 = __hfma2(tanh2_hw(__hmul2(ar2, H05)), H05, H05);
                // candidate: tanh(xh + r*rh)
                __half2 hc2 = tanh2_hw(__hfma2(r2, ah2, ax2));
                // update: hnew = hc + z*(hold - hc)
                __half2 hold2 = *(__half2*)&hh_[r];
                __half2 hn2 = __hfma2(z2, __hsub2(hold2, hc2), hc2);
                nh[r] = *(uint32_t*)&hn2;
                if (t == TSTEPS - 1) {
                    float2 f = __half22float2(hn2);
                    int row = mt * 16 + gid + 8 * (r & 1);
                    int j   = 16 * wid + 8 * nt + 2 * tg;
                    hs[row][j]     = f.x;
                    hs[row][j + 1] = f.y;
                }
            }
            Ah[q][wid][mt][lane] = make_uint4(nh[0], nh[1], nh[2], nh[3]);
        }

        if (t < TSTEPS - 1) st_x(q, pv0, pv1);
        __syncthreads();   // buf q complete + all buf p reads done -> next step
    }

    // ---- dense + softmax ----
    if (tid < TILE_B) {
        const int row = tid;
        float lg[NCLS];
#pragma unroll
        for (int c = 0; c < NCLS; c++) lg[c] = db[c];
        for (int j = 0; j < HID; j++) {
            float hv = hs[row][j];
#pragma unroll
            for (int c = 0; c < NCLS; c++) lg[c] = fmaf(hv, dw[j * NCLS + c], lg[c]);
        }
        float m = lg[0];
#pragma unroll
        for (int c = 1; c < NCLS; c++) m = fmaxf(m, lg[c]);
        float s = 0.0f;
#pragma unroll
        for (int c = 0; c < NCLS; c++) { lg[c] = expf(lg[c] - m); s += lg[c]; }
        float inv = __fdividef(1.0f, s);
#pragma unroll
        for (int c = 0; c < NCLS; c++)
            out[(size_t)(b0 + row) * NCLS + c] = lg[c] * inv;
    }
}

extern "C" void kernel_launch(void* const* d_in, const int* in_sizes, int n_in,
                              void* d_out, int out_size) {
    const float* x    = (const float*)d_in[0];
    const float* Wk   = (const float*)d_in[1];
    const float* Rk   = (const float*)d_in[2];
    const float* bias = (const float*)d_in[3];
    const float* dw   = (const float*)d_in[4];
    const float* db   = (const float*)d_in[5];
    float* out = (float*)d_out;

    prep_B<<<(NBFR4 + 255) / 256, 256>>>(Rk, Wk);
    gru_hmma_kernel<<<NBLK, NTH>>>(x, bias, dw, db, out);
}